// round 10
// baseline (speedup 1.0000x reference)
#include <cuda_runtime.h>
#include <cuda_bf16.h>
#include <cstdint>
#include <math.h>

// Problem constants (fixed shapes)
#define B_   2
#define T_   2048
#define D_   2048
#define H_   16
#define HD_  128
#define M_   (B_ * T_)      // 4096 rows
#define N1_  (3 * D_)       // 6144 qkv cols
#define SCALE_ 0.022097086912079612f   // 2048^-0.5  (D, not head_dim!)

// ---------------------------------------------------------------------------
// Scratch (device globals — no allocation allowed)
// ---------------------------------------------------------------------------
__device__ float g_qkv[(size_t)M_ * N1_];          // 100.7 MB
// bf16 split operands
__device__ __nv_bfloat16 g_xh[(size_t)M_ * D_];
__device__ __nv_bfloat16 g_xl[(size_t)M_ * D_];
__device__ __nv_bfloat16 g_wqh[(size_t)N1_ * D_];
__device__ __nv_bfloat16 g_wql[(size_t)N1_ * D_];
__device__ __nv_bfloat16 g_ah[(size_t)M_ * D_];
__device__ __nv_bfloat16 g_al[(size_t)M_ * D_];
__device__ __nv_bfloat16 g_wh[(size_t)D_ * D_];
__device__ __nv_bfloat16 g_wl[(size_t)D_ * D_];
// roped q/k and v, bf16 hi/lo, layout [bh][t][hd]
#define QKV_ELEMS ((size_t)B_ * H_ * T_ * HD_)
__device__ __nv_bfloat16 g_qh[QKV_ELEMS];
__device__ __nv_bfloat16 g_ql[QKV_ELEMS];
__device__ __nv_bfloat16 g_kh[QKV_ELEMS];
__device__ __nv_bfloat16 g_kl[QKV_ELEMS];
__device__ __nv_bfloat16 g_vh[QKV_ELEMS];
__device__ __nv_bfloat16 g_vl[QKV_ELEMS];

// ---------------------------------------------------------------------------
// PTX helpers (family-portable: ldmatrix / mma.sync / cp.async)
// ---------------------------------------------------------------------------
__device__ __forceinline__ uint32_t smem_to_u32(const void* p) {
    uint32_t a;
    asm("{ .reg .u64 t; cvta.to.shared.u64 t, %1; cvt.u32.u64 %0, t; }"
        : "=r"(a) : "l"(p));
    return a;
}
#define SMEM_SWIZZLE_128B(off) ((off) ^ (((off) >> 3) & 0x70))

#define CP_ASYNC16(dst, src) \
    asm volatile("cp.async.cg.shared.global [%0], [%1], 16;" \
                 :: "r"((uint32_t)(dst)), "l"(src))
#define CP_ASYNC_COMMIT() asm volatile("cp.async.commit_group;" ::: "memory")

__device__ __forceinline__ void ldsm4(uint32_t* r, uint32_t addr) {
    asm volatile("ldmatrix.sync.aligned.m8n8.x4.shared.b16 {%0,%1,%2,%3}, [%4];"
                 : "=r"(r[0]), "=r"(r[1]), "=r"(r[2]), "=r"(r[3]) : "r"(addr));
}
__device__ __forceinline__ void ldsm4t(uint32_t* r, uint32_t addr) {
    asm volatile("ldmatrix.sync.aligned.m8n8.x4.trans.shared.b16 {%0,%1,%2,%3}, [%4];"
                 : "=r"(r[0]), "=r"(r[1]), "=r"(r[2]), "=r"(r[3]) : "r"(addr));
}

__device__ __forceinline__ void mma16816(float* c, const uint32_t* a,
                                         uint32_t b0, uint32_t b1) {
    asm volatile(
        "mma.sync.aligned.m16n8k16.row.col.f32.bf16.bf16.f32 "
        "{%0,%1,%2,%3}, {%4,%5,%6,%7}, {%8,%9}, {%0,%1,%2,%3};"
        : "+f"(c[0]), "+f"(c[1]), "+f"(c[2]), "+f"(c[3])
        : "r"(a[0]), "r"(a[1]), "r"(a[2]), "r"(a[3]), "r"(b0), "r"(b1));
}

__device__ __forceinline__ void pack_hl(float p0, float p1,
                                        uint32_t& h, uint32_t& l) {
    __nv_bfloat162 hh = __floats2bfloat162_rn(p0, p1);
    float r0 = p0 - __bfloat162float(hh.x);
    float r1 = p1 - __bfloat162float(hh.y);
    __nv_bfloat162 ll = __floats2bfloat162_rn(r0, r1);
    h = *(uint32_t*)&hh;
    l = *(uint32_t*)&ll;
}

// ---------------------------------------------------------------------------
// fp32 -> (bf16 hi, bf16 lo) split, vectorized
// ---------------------------------------------------------------------------
__global__ __launch_bounds__(256) void split_bf16(
    const float* __restrict__ src, __nv_bfloat16* __restrict__ hi,
    __nv_bfloat16* __restrict__ lo)
{
    const int i = blockIdx.x * 256 + threadIdx.x;   // float4 index
    float4 v = ((const float4*)src)[i];
    uint32_t h0, l0, h1, l1;
    pack_hl(v.x, v.y, h0, l0);
    pack_hl(v.z, v.w, h1, l1);
    ((uint2*)hi)[i] = make_uint2(h0, h1);
    ((uint2*)lo)[i] = make_uint2(l0, l1);
}

// ---------------------------------------------------------------------------
// HMMA GEMM: C[M,N] = A[M,K] @ W[N,K]^T + bias   (bf16 3-term split)
// CTA 128x128, BK=64, 8 warps (2m x 4n), warp tile 64x32.
// 3-stage cp.async pipeline: 3 x 64KB buffers, loads 2 chunks ahead,
// ONE __syncthreads per chunk (it both publishes chunk c and proves all
// warps finished chunk c-1, freeing buffer (c+2)%3 for the next load).
// Tiles: 128 rows x 64 bf16 (128B rows), SW128 swizzle.
// ---------------------------------------------------------------------------
#define GEMM_SMEM_BYTES (3 * 65536 + 1024)

__device__ __forceinline__ void load_chunk(
    const __nv_bfloat16* Ah, const __nv_bfloat16* Al,
    const __nv_bfloat16* Bh, const __nv_bfloat16* Bl,
    int bm, int bn, int K, int k0, uint32_t dbase, int tid)
{
#pragma unroll
    for (int i = 0; i < 16; i++) {
        const int idx = tid + i * 256;
        const int t   = idx >> 10;
        const int r   = (idx >> 3) & 127;
        const int c16 = idx & 7;
        const __nv_bfloat16* sp;
        int row;
        if (t == 0)      { sp = Ah; row = bm + r; }
        else if (t == 1) { sp = Al; row = bm + r; }
        else if (t == 2) { sp = Bh; row = bn + r; }
        else             { sp = Bl; row = bn + r; }
        const char* src = (const char*)sp +
            (((size_t)row * K + k0) << 1) + (c16 << 4);
        const uint32_t off = (r << 7) + (c16 << 4);
        const uint32_t dst = dbase + (t << 14) + SMEM_SWIZZLE_128B(off);
        CP_ASYNC16(dst, src);
    }
    CP_ASYNC_COMMIT();
}

__global__ __launch_bounds__(256, 1) void gemm_hmma(
    const __nv_bfloat16* __restrict__ Ah, const __nv_bfloat16* __restrict__ Al,
    const __nv_bfloat16* __restrict__ Bh, const __nv_bfloat16* __restrict__ Bl,
    const float* __restrict__ bias, float* __restrict__ C,
    int M, int N, int K)
{
    extern __shared__ __align__(16) char smem[];
    const uint32_t data0 = (smem_to_u32(smem) + 1023) & ~1023u;

    const int tid  = threadIdx.x;
    const int lane = tid & 31;
    const int wid  = tid >> 5;
    const int warp_m = wid >> 2;
    const int warp_n = wid & 3;
    const int bm = blockIdx.y * 128;
    const int bn = blockIdx.x * 128;

    const uint32_t a_row = warp_m * 64 + (lane & 15);
    const uint32_t a_kb  = (uint32_t)(lane >> 4) << 4;
    const uint32_t b_row = warp_n * 32 + (lane & 7) + (((uint32_t)lane >> 4) << 3);
    const uint32_t b_kb  = (((uint32_t)lane >> 3) & 1) << 4;

    float acc[4][4][4];
#pragma unroll
    for (int mt = 0; mt < 4; mt++)
#pragma unroll
        for (int nt = 0; nt < 4; nt++)
#pragma unroll
            for (int r = 0; r < 4; r++) acc[mt][nt][r] = 0.0f;

    const int nchunks = K >> 6;              // BK = 64

    // Prologue: prefetch chunks 0 and 1.
    load_chunk(Ah, Al, Bh, Bl, bm, bn, K, 0,       data0,          tid);
    load_chunk(Ah, Al, Bh, Bl, bm, bn, K, 1 << 6,  data0 + 65536,  tid);

    uint32_t buf = 0;  // buffer index of current chunk (0,1,2 cyclic)
    for (int c = 0; c < nchunks; c++) {
        // Wait for chunk c's group (keep at most 1 newer group pending).
        if (c < nchunks - 1) {
            asm volatile("cp.async.wait_group 1;" ::: "memory");
        } else {
            asm volatile("cp.async.wait_group 0;" ::: "memory");
        }
        // Publishes chunk c to all warps AND proves every warp finished
        // computing chunk c-1 (whose buffer (c+2)%3 we overwrite next).
        __syncthreads();

        if (c + 2 < nchunks) {
            const uint32_t nbuf = (buf + 2 >= 3) ? buf - 1 : buf + 2;
            load_chunk(Ah, Al, Bh, Bl, bm, bn, K, (c + 2) << 6,
                       data0 + nbuf * 65536, tid);
        }

        const uint32_t dbase = data0 + buf * 65536;
        const uint32_t sAh = dbase;
        const uint32_t sAl = dbase + 16384;
        const uint32_t sBh = dbase + 32768;
        const uint32_t sBl = dbase + 49152;

#pragma unroll
        for (int ks = 0; ks < 4; ks++) {
            const uint32_t kbyte = (uint32_t)ks << 5;

            uint32_t af_h[4][4], af_l[4][4];
#pragma unroll
            for (int mt = 0; mt < 4; mt++) {
                const uint32_t off = ((a_row + mt * 16) << 7) + kbyte + a_kb;
                const uint32_t sw = SMEM_SWIZZLE_128B(off);
                ldsm4(af_h[mt], sAh + sw);
                ldsm4(af_l[mt], sAl + sw);
            }
            uint32_t bf_h[2][4], bf_l[2][4];
#pragma unroll
            for (int ng = 0; ng < 2; ng++) {
                const uint32_t off = ((b_row + ng * 16) << 7) + kbyte + b_kb;
                const uint32_t sw = SMEM_SWIZZLE_128B(off);
                ldsm4(bf_h[ng], sBh + sw);
                ldsm4(bf_l[ng], sBl + sw);
            }
#pragma unroll
            for (int mt = 0; mt < 4; mt++) {
#pragma unroll
                for (int nt = 0; nt < 4; nt++) {
                    const int ng = nt >> 1, lo = (nt & 1) * 2;
                    mma16816(acc[mt][nt], af_h[mt], bf_h[ng][lo], bf_h[ng][lo + 1]);
                    mma16816(acc[mt][nt], af_h[mt], bf_l[ng][lo], bf_l[ng][lo + 1]);
                    mma16816(acc[mt][nt], af_l[mt], bf_h[ng][lo], bf_h[ng][lo + 1]);
                }
            }
        }
        buf = (buf + 1 >= 3) ? 0 : buf + 1;
    }

    const int gm0 = bm + warp_m * 64 + (lane >> 2);
    const int gn0 = bn + warp_n * 32 + (lane & 3) * 2;
#pragma unroll
    for (int mt = 0; mt < 4; mt++) {
#pragma unroll
        for (int nt = 0; nt < 4; nt++) {
            const int gm = gm0 + mt * 16;
            const int gn = gn0 + nt * 8;
            const float b0 = bias[gn], b1 = bias[gn + 1];
            float2 v0 = make_float2(acc[mt][nt][0] + b0, acc[mt][nt][1] + b1);
            float2 v1 = make_float2(acc[mt][nt][2] + b0, acc[mt][nt][3] + b1);
            *(float2*)&C[(size_t)gm * N + gn]       = v0;
            *(float2*)&C[(size_t)(gm + 8) * N + gn] = v1;
        }
    }
}

// ---------------------------------------------------------------------------
// RoPE + split qkv -> q/k/v bf16 hi/lo, layout [bh][t][hd]
// ---------------------------------------------------------------------------
__device__ __forceinline__ void st_hl(float v, __nv_bfloat16* hi,
                                      __nv_bfloat16* lo, size_t idx) {
    __nv_bfloat16 h = __float2bfloat16(v);
    hi[idx] = h;
    lo[idx] = __float2bfloat16(v - __bfloat162float(h));
}

__global__ __launch_bounds__(256) void rope_split_hl(
    const float* __restrict__ qkv,
    __nv_bfloat16* __restrict__ qh, __nv_bfloat16* __restrict__ ql,
    __nv_bfloat16* __restrict__ kh, __nv_bfloat16* __restrict__ kl,
    __nv_bfloat16* __restrict__ vh, __nv_bfloat16* __restrict__ vl)
{
    const int idx = blockIdx.x * blockDim.x + threadIdx.x;
    const int i  = idx & 63;
    const int t  = (idx >> 6) & (T_ - 1);
    const int h  = (idx >> 17) & (H_ - 1);
    const int b  = idx >> 21;
    const int bh = idx >> 17;

    const float* src = qkv + ((size_t)(b * T_ + t)) * N1_ + h * (3 * HD_);
    const float q1 = src[i],        q2 = src[64 + i];
    const float k1 = src[128 + i],  k2 = src[192 + i];
    const float v1 = src[256 + i],  v2 = src[320 + i];

    const float theta = powf(10000.0f, -(float)i * (1.0f / 64.0f));
    const float ang = (float)t * theta;
    const float cs = cosf(ang), sn = sinf(ang);

    const size_t dst = ((size_t)bh * T_ + t) * HD_ + i;
    st_hl(q1 * cs - q2 * sn, qh, ql, dst);
    st_hl(q1 * sn + q2 * cs, qh, ql, dst + 64);
    st_hl(k1 * cs - k2 * sn, kh, kl, dst);
    st_hl(k1 * sn + k2 * cs, kh, kl, dst + 64);
    st_hl(v1, vh, vl, dst);
    st_hl(v2, vh, vl, dst + 64);
}

// ---------------------------------------------------------------------------
// Causal flash attention on mma.sync bf16 (3-term splits).
// (unchanged from R7 passing version)
// ---------------------------------------------------------------------------
#define FL_SMEM_BYTES 208896
#define FL_STRIDE 272

__device__ __forceinline__ void fl_load_kv(
    const __nv_bfloat16* Kh, const __nv_bfloat16* Kl,
    const __nv_bfloat16* Vh, const __nv_bfloat16* Vl,
    size_t goff, uint32_t sbuf, int tid)
{
#pragma unroll
    for (int i = 0; i < 16; i++) {
        const int idx = tid + i * 256;
        const int arr = idx >> 10;          // 0:Kh 1:Kl 2:Vh 3:Vl
        const int r   = (idx >> 4) & 63;
        const int seg = idx & 15;
        const __nv_bfloat16* p = (arr == 0) ? Kh : (arr == 1) ? Kl
                               : (arr == 2) ? Vh : Vl;
        const char* src = (const char*)p + ((goff + (size_t)r * HD_) << 1) + (seg << 4);
        const uint32_t dst = sbuf + arr * 17408 + r * FL_STRIDE + (seg << 4);
        CP_ASYNC16(dst, src);
    }
    CP_ASYNC_COMMIT();
}

__global__ __launch_bounds__(256, 1) void flash_hmma(
    const __nv_bfloat16* __restrict__ Qh, const __nv_bfloat16* __restrict__ Ql,
    const __nv_bfloat16* __restrict__ Kh, const __nv_bfloat16* __restrict__ Kl,
    const __nv_bfloat16* __restrict__ Vh, const __nv_bfloat16* __restrict__ Vl,
    __nv_bfloat16* __restrict__ Oh, __nv_bfloat16* __restrict__ Ol)
{
    extern __shared__ __align__(16) char smc[];
    const uint32_t sb  = smem_to_u32(smc);
    const uint32_t sQh = sb, sQl = sb + 34816;
    const uint32_t sKV = sb + 69632;            // + buf*69632

    const int tid  = threadIdx.x;
    const int lane = tid & 31;
    const int warp = tid >> 5;
    const int qt = 15 - (int)blockIdx.x;        // heavy blocks first
    const int bh = blockIdx.y;
    const int b = bh >> 4, h = bh & 15;
    const size_t gbase = (size_t)bh * T_ * HD_;

    // Q load (hi + lo)
    {
        const size_t qoff = gbase + (size_t)qt * 128 * HD_;
#pragma unroll
        for (int i = 0; i < 16; i++) {
            const int idx = tid + i * 256;
            const int arr = idx >> 11;
            const int r   = (idx >> 4) & 127;
            const int seg = idx & 15;
            const char* src = (const char*)(arr ? Ql : Qh) +
                ((qoff + (size_t)r * HD_) << 1) + (seg << 4);
            const uint32_t dst = (arr ? sQl : sQh) + r * FL_STRIDE + (seg << 4);
            CP_ASYNC16(dst, src);
        }
        CP_ASYNC_COMMIT();
    }
    // first KV tile
    fl_load_kv(Kh, Kl, Vh, Vl, gbase, sKV, tid);

    const int r0w = warp * 16;
    const uint32_t aoff = (r0w + (lane & 15)) * FL_STRIDE + ((lane >> 4) << 4);
    const uint32_t boff = ((lane & 7) + ((lane >> 4) << 3)) * FL_STRIDE +
                          (((lane >> 3) & 1) << 4);
    const uint32_t vrow = (lane & 7) + (((lane >> 3) & 1) << 3);
    const uint32_t vcol = (lane >> 4) << 4;

    float o[16][4];
#pragma unroll
    for (int nt = 0; nt < 16; nt++)
#pragma unroll
        for (int r = 0; r < 4; r++) o[nt][r] = 0.0f;
    float m_[2] = {-1e30f, -1e30f};
    float l_[2] = {0.0f, 0.0f};

    const int ktmax = 2 * qt + 1;
    for (int kt = 0; kt <= ktmax; kt++) {
        if (kt > 0) __syncthreads();
        if (kt < ktmax) {
            fl_load_kv(Kh, Kl, Vh, Vl, gbase + (size_t)(kt + 1) * 64 * HD_,
                       sKV + ((kt + 1) & 1) * 69632, tid);
            asm volatile("cp.async.wait_group 1;" ::: "memory");
        } else {
            asm volatile("cp.async.wait_group 0;" ::: "memory");
        }
        __syncthreads();

        const uint32_t kb = sKV + (kt & 1) * 69632;
        const uint32_t sKh = kb, sKl = kb + 17408;
        const uint32_t sVh = kb + 34816, sVl = kb + 52224;

        // ---- S = Q K^T (3-term) ----
        float s[8][4];
#pragma unroll
        for (int nt = 0; nt < 8; nt++)
#pragma unroll
            for (int r = 0; r < 4; r++) s[nt][r] = 0.0f;

#pragma unroll
        for (int ks = 0; ks < 8; ks++) {
            const uint32_t kbyte = (uint32_t)ks << 5;
            uint32_t ah_[4], al_[4];
            ldsm4(ah_, sQh + aoff + kbyte);
            ldsm4(al_, sQl + aoff + kbyte);
            uint32_t bh_[4][4], bl_[4][4];
#pragma unroll
            for (int np = 0; np < 4; np++) {
                const uint32_t off = boff + np * 16 * FL_STRIDE + kbyte;
                ldsm4(bh_[np], sKh + off);
                ldsm4(bl_[np], sKl + off);
            }
#pragma unroll
            for (int nt = 0; nt < 8; nt++) {
                const int ng = nt >> 1, lo = (nt & 1) * 2;
                mma16816(s[nt], ah_, bh_[ng][lo], bh_[ng][lo + 1]);
                mma16816(s[nt], ah_, bl_[ng][lo], bl_[ng][lo + 1]);
                mma16816(s[nt], al_, bh_[ng][lo], bh_[ng][lo + 1]);
            }
        }

        // ---- scale + mask + online softmax ----
        const int qa = qt * 128 + r0w + (lane >> 2);
        const int qb = qa + 8;
        const bool dg = (kt >= 2 * qt);
#pragma unroll
        for (int nt = 0; nt < 8; nt++) {
            const int c0 = kt * 64 + nt * 8 + (lane & 3) * 2;
            s[nt][0] *= SCALE_; s[nt][1] *= SCALE_;
            s[nt][2] *= SCALE_; s[nt][3] *= SCALE_;
            if (dg) {
                if (c0     > qa) s[nt][0] = -1e30f;
                if (c0 + 1 > qa) s[nt][1] = -1e30f;
                if (c0     > qb) s[nt][2] = -1e30f;
                if (c0 + 1 > qb) s[nt][3] = -1e30f;
            }
        }
        float ma = -1e30f, mb = -1e30f;
#pragma unroll
        for (int nt = 0; nt < 8; nt++) {
            ma = fmaxf(ma, fmaxf(s[nt][0], s[nt][1]));
            mb = fmaxf(mb, fmaxf(s[nt][2], s[nt][3]));
        }
        ma = fmaxf(ma, __shfl_xor_sync(0xFFFFFFFF, ma, 1));
        ma = fmaxf(ma, __shfl_xor_sync(0xFFFFFFFF, ma, 2));
        mb = fmaxf(mb, __shfl_xor_sync(0xFFFFFFFF, mb, 1));
        mb = fmaxf(mb, __shfl_xor_sync(0xFFFFFFFF, mb, 2));
        const float mna = fmaxf(m_[0], ma), mnb = fmaxf(m_[1], mb);
        const float ca = __expf(m_[0] - mna), cb = __expf(m_[1] - mnb);
        float suma = 0.0f, sumb = 0.0f;
#pragma unroll
        for (int nt = 0; nt < 8; nt++) {
            s[nt][0] = __expf(s[nt][0] - mna); suma += s[nt][0];
            s[nt][1] = __expf(s[nt][1] - mna); suma += s[nt][1];
            s[nt][2] = __expf(s[nt][2] - mnb); sumb += s[nt][2];
            s[nt][3] = __expf(s[nt][3] - mnb); sumb += s[nt][3];
        }
        suma += __shfl_xor_sync(0xFFFFFFFF, suma, 1);
        suma += __shfl_xor_sync(0xFFFFFFFF, suma, 2);
        sumb += __shfl_xor_sync(0xFFFFFFFF, sumb, 1);
        sumb += __shfl_xor_sync(0xFFFFFFFF, sumb, 2);
        l_[0] = l_[0] * ca + suma;  m_[0] = mna;
        l_[1] = l_[1] * cb + sumb;  m_[1] = mnb;
#pragma unroll
        for (int nt = 0; nt < 16; nt++) {
            o[nt][0] *= ca; o[nt][1] *= ca;
            o[nt][2] *= cb; o[nt][3] *= cb;
        }

        // ---- P fragments (bf16 hi/lo) ----
        uint32_t pa_h[4][4], pa_l[4][4];
#pragma unroll
        for (int j = 0; j < 4; j++) {
            pack_hl(s[2 * j][0],     s[2 * j][1],     pa_h[j][0], pa_l[j][0]);
            pack_hl(s[2 * j][2],     s[2 * j][3],     pa_h[j][1], pa_l[j][1]);
            pack_hl(s[2 * j + 1][0], s[2 * j + 1][1], pa_h[j][2], pa_l[j][2]);
            pack_hl(s[2 * j + 1][2], s[2 * j + 1][3], pa_h[j][3], pa_l[j][3]);
        }

        // ---- O += P V (3-term), V via ldmatrix.trans ----
#pragma unroll
        for (int j = 0; j < 4; j++) {
            const uint32_t rbase = (j * 16 + vrow) * FL_STRIDE + vcol;
#pragma unroll
            for (int dp = 0; dp < 8; dp++) {
                uint32_t vh_[4], vl_[4];
                const uint32_t off = rbase + dp * 32;
                ldsm4t(vh_, sVh + off);
                ldsm4t(vl_, sVl + off);
                const int nt0 = dp * 2, nt1 = nt0 + 1;
                mma16816(o[nt0], pa_h[j], vh_[0], vh_[1]);
                mma16816(o[nt0], pa_l[j], vh_[0], vh_[1]);
                mma16816(o[nt0], pa_h[j], vl_[0], vl_[1]);
                mma16816(o[nt1], pa_h[j], vh_[2], vh_[3]);
                mma16816(o[nt1], pa_l[j], vh_[2], vh_[3]);
                mma16816(o[nt1], pa_h[j], vl_[2], vl_[3]);
            }
        }
    }

    // ---- epilogue: normalize, write bf16 hi/lo to [B*T][D] ----
    const float inva = 1.0f / l_[0], invb = 1.0f / l_[1];
    const int ta = qt * 128 + r0w + (lane >> 2);
    const size_t rowa = (size_t)(b * T_ + ta) * D_;
    const size_t rowb = rowa + 8 * D_;
    const int cb0 = h * HD_ + (lane & 3) * 2;
#pragma unroll
    for (int nt = 0; nt < 16; nt++) {
        const size_t ia = rowa + cb0 + nt * 8;
        const size_t ib = rowb + cb0 + nt * 8;
        uint32_t hA, lA, hB, lB;
        pack_hl(o[nt][0] * inva, o[nt][1] * inva, hA, lA);
        pack_hl(o[nt][2] * invb, o[nt][3] * invb, hB, lB);
        *(uint32_t*)(Oh + ia) = hA;  *(uint32_t*)(Ol + ia) = lA;
        *(uint32_t*)(Oh + ib) = hB;  *(uint32_t*)(Ol + ib) = lB;
    }
}

// ---------------------------------------------------------------------------
// kernel_launch
// ---------------------------------------------------------------------------
extern "C" void kernel_launch(void* const* d_in, const int* in_sizes, int n_in,
                              void* d_out, int out_size)
{
    const float* x     = (const float*)d_in[0];
    const float* w_qkv = (const float*)d_in[1];
    const float* b_qkv = (const float*)d_in[2];
    const float* w_out = (const float*)d_in[3];
    const float* b_out = (const float*)d_in[4];
    float* out = (float*)d_out;

    float* qkv;
    cudaGetSymbolAddress((void**)&qkv, g_qkv);
    __nv_bfloat16 *xh, *xl, *wqh, *wql, *ah, *al, *wh, *wl;
    __nv_bfloat16 *qh, *ql, *kh, *kl, *vh, *vl;
    cudaGetSymbolAddress((void**)&xh,  g_xh);
    cudaGetSymbolAddress((void**)&xl,  g_xl);
    cudaGetSymbolAddress((void**)&wqh, g_wqh);
    cudaGetSymbolAddress((void**)&wql, g_wql);
    cudaGetSymbolAddress((void**)&ah,  g_ah);
    cudaGetSymbolAddress((void**)&al,  g_al);
    cudaGetSymbolAddress((void**)&wh,  g_wh);
    cudaGetSymbolAddress((void**)&wl,  g_wl);
    cudaGetSymbolAddress((void**)&qh,  g_qh);
    cudaGetSymbolAddress((void**)&ql,  g_ql);
    cudaGetSymbolAddress((void**)&kh,  g_kh);
    cudaGetSymbolAddress((void**)&kl,  g_kl);
    cudaGetSymbolAddress((void**)&vh,  g_vh);
    cudaGetSymbolAddress((void**)&vl,  g_vl);

    cudaFuncSetAttribute(gemm_hmma,
                         cudaFuncAttributeMaxDynamicSharedMemorySize,
                         GEMM_SMEM_BYTES);
    cudaFuncSetAttribute(flash_hmma,
                         cudaFuncAttributeMaxDynamicSharedMemorySize,
                         FL_SMEM_BYTES);

    // 0) split x / w_qkv into bf16 hi/lo
    split_bf16<<<((size_t)M_ * D_) / 1024, 256>>>(x, xh, xl);
    split_bf16<<<((size_t)N1_ * D_) / 1024, 256>>>(w_qkv, wqh, wql);
    // 1) qkv = x @ w_qkv^T + b_qkv   (HMMA)
    gemm_hmma<<<dim3(N1_ / 128, M_ / 128), 256, GEMM_SMEM_BYTES>>>(
        xh, xl, wqh, wql, b_qkv, qkv, M_, N1_, D_);
    // 2) RoPE + head split -> bf16 hi/lo
    rope_split_hl<<<(B_ * H_ * T_ * 64) / 256, 256>>>(qkv, qh, ql, kh, kl, vh, vl);
    // 3) causal flash attention (HMMA) -> attn bf16 hi/lo directly
    flash_hmma<<<dim3(16, B_ * H_), 256, FL_SMEM_BYTES>>>(
        qh, ql, kh, kl, vh, vl, ah, al);
    // 4) out = attn @ w_out^T + b_out  (HMMA)
    split_bf16<<<((size_t)D_ * D_) / 1024, 256>>>(w_out, wh, wl);
    gemm_hmma<<<dim3(D_ / 128, M_ / 128), 256, GEMM_SMEM_BYTES>>>(
        ah, al, wh, wl, b_out, out, M_, D_, D_);
}

// round 11
// speedup vs baseline: 1.5147x; 1.5147x over previous
#include <cuda_runtime.h>
#include <cuda_bf16.h>
#include <cstdint>
#include <math.h>

// Problem constants (fixed shapes)
#define B_   2
#define T_   2048
#define D_   2048
#define H_   16
#define HD_  128
#define M_   (B_ * T_)      // 4096 rows
#define N1_  (3 * D_)       // 6144 qkv cols
#define SCALE_ 0.022097086912079612f   // 2048^-0.5  (D, not head_dim!)

// ---------------------------------------------------------------------------
// Scratch (device globals — no allocation allowed)
// ---------------------------------------------------------------------------
__device__ float g_qkv[(size_t)M_ * N1_];          // 100.7 MB
// bf16 split operands
__device__ __nv_bfloat16 g_xh[(size_t)M_ * D_];
__device__ __nv_bfloat16 g_xl[(size_t)M_ * D_];
__device__ __nv_bfloat16 g_wqh[(size_t)N1_ * D_];
__device__ __nv_bfloat16 g_wql[(size_t)N1_ * D_];
__device__ __nv_bfloat16 g_ah[(size_t)M_ * D_];
__device__ __nv_bfloat16 g_al[(size_t)M_ * D_];
__device__ __nv_bfloat16 g_wh[(size_t)D_ * D_];
__device__ __nv_bfloat16 g_wl[(size_t)D_ * D_];
// roped q/k and v, bf16 hi/lo, layout [bh][t][hd]
#define QKV_ELEMS ((size_t)B_ * H_ * T_ * HD_)
__device__ __nv_bfloat16 g_qh[QKV_ELEMS];
__device__ __nv_bfloat16 g_ql[QKV_ELEMS];
__device__ __nv_bfloat16 g_kh[QKV_ELEMS];
__device__ __nv_bfloat16 g_kl[QKV_ELEMS];
__device__ __nv_bfloat16 g_vh[QKV_ELEMS];
__device__ __nv_bfloat16 g_vl[QKV_ELEMS];

// ---------------------------------------------------------------------------
// PTX helpers (family-portable: ldmatrix / mma.sync / cp.async)
// ---------------------------------------------------------------------------
__device__ __forceinline__ uint32_t smem_to_u32(const void* p) {
    uint32_t a;
    asm("{ .reg .u64 t; cvta.to.shared.u64 t, %1; cvt.u32.u64 %0, t; }"
        : "=r"(a) : "l"(p));
    return a;
}
#define SMEM_SWIZZLE_128B(off) ((off) ^ (((off) >> 3) & 0x70))

#define CP_ASYNC16(dst, src) \
    asm volatile("cp.async.cg.shared.global [%0], [%1], 16;" \
                 :: "r"((uint32_t)(dst)), "l"(src))
#define CP_ASYNC_COMMIT() asm volatile("cp.async.commit_group;" ::: "memory")

__device__ __forceinline__ void ldsm4(uint32_t* r, uint32_t addr) {
    asm volatile("ldmatrix.sync.aligned.m8n8.x4.shared.b16 {%0,%1,%2,%3}, [%4];"
                 : "=r"(r[0]), "=r"(r[1]), "=r"(r[2]), "=r"(r[3]) : "r"(addr));
}
__device__ __forceinline__ void ldsm4t(uint32_t* r, uint32_t addr) {
    asm volatile("ldmatrix.sync.aligned.m8n8.x4.trans.shared.b16 {%0,%1,%2,%3}, [%4];"
                 : "=r"(r[0]), "=r"(r[1]), "=r"(r[2]), "=r"(r[3]) : "r"(addr));
}

__device__ __forceinline__ void mma16816(float* c, const uint32_t* a,
                                         uint32_t b0, uint32_t b1) {
    asm volatile(
        "mma.sync.aligned.m16n8k16.row.col.f32.bf16.bf16.f32 "
        "{%0,%1,%2,%3}, {%4,%5,%6,%7}, {%8,%9}, {%0,%1,%2,%3};"
        : "+f"(c[0]), "+f"(c[1]), "+f"(c[2]), "+f"(c[3])
        : "r"(a[0]), "r"(a[1]), "r"(a[2]), "r"(a[3]), "r"(b0), "r"(b1));
}

__device__ __forceinline__ void pack_hl(float p0, float p1,
                                        uint32_t& h, uint32_t& l) {
    __nv_bfloat162 hh = __floats2bfloat162_rn(p0, p1);
    float r0 = p0 - __bfloat162float(hh.x);
    float r1 = p1 - __bfloat162float(hh.y);
    __nv_bfloat162 ll = __floats2bfloat162_rn(r0, r1);
    h = *(uint32_t*)&hh;
    l = *(uint32_t*)&ll;
}

// ---------------------------------------------------------------------------
// fp32 -> (bf16 hi, bf16 lo) split, vectorized
// ---------------------------------------------------------------------------
__global__ __launch_bounds__(256) void split_bf16(
    const float* __restrict__ src, __nv_bfloat16* __restrict__ hi,
    __nv_bfloat16* __restrict__ lo)
{
    const int i = blockIdx.x * 256 + threadIdx.x;   // float4 index
    float4 v = ((const float4*)src)[i];
    uint32_t h0, l0, h1, l1;
    pack_hl(v.x, v.y, h0, l0);
    pack_hl(v.z, v.w, h1, l1);
    ((uint2*)hi)[i] = make_uint2(h0, h1);
    ((uint2*)lo)[i] = make_uint2(l0, l1);
}

// ---------------------------------------------------------------------------
// HMMA GEMM: C[M,N] = A[M,K] @ W[N,K]^T + bias   (bf16 3-term split)
// CTA 128x128, BK=64, 8 warps (2m x 4n), warp tile 64x32.
// R7 structure (2 x 64KB buffers, wait_group 1, two syncs per chunk) +
// register-level fragment double-buffering: ldsm for k-step ks+1 issues
// while the 48 HMMAs of k-step ks execute, hiding LDS latency in-warp.
// ---------------------------------------------------------------------------
#define GEMM_SMEM_BYTES (131072 + 1024)

__device__ __forceinline__ void load_chunk(
    const __nv_bfloat16* Ah, const __nv_bfloat16* Al,
    const __nv_bfloat16* Bh, const __nv_bfloat16* Bl,
    int bm, int bn, int K, int k0, uint32_t dbase, int tid)
{
#pragma unroll
    for (int i = 0; i < 16; i++) {
        const int idx = tid + i * 256;
        const int t   = idx >> 10;
        const int r   = (idx >> 3) & 127;
        const int c16 = idx & 7;
        const __nv_bfloat16* sp;
        int row;
        if (t == 0)      { sp = Ah; row = bm + r; }
        else if (t == 1) { sp = Al; row = bm + r; }
        else if (t == 2) { sp = Bh; row = bn + r; }
        else             { sp = Bl; row = bn + r; }
        const char* src = (const char*)sp +
            (((size_t)row * K + k0) << 1) + (c16 << 4);
        const uint32_t off = (r << 7) + (c16 << 4);
        const uint32_t dst = dbase + (t << 14) + SMEM_SWIZZLE_128B(off);
        CP_ASYNC16(dst, src);
    }
    CP_ASYNC_COMMIT();
}

__global__ __launch_bounds__(256, 1) void gemm_hmma(
    const __nv_bfloat16* __restrict__ Ah, const __nv_bfloat16* __restrict__ Al,
    const __nv_bfloat16* __restrict__ Bh, const __nv_bfloat16* __restrict__ Bl,
    const float* __restrict__ bias, float* __restrict__ C,
    int M, int N, int K)
{
    extern __shared__ __align__(16) char smem[];
    const uint32_t data0 = (smem_to_u32(smem) + 1023) & ~1023u;

    const int tid  = threadIdx.x;
    const int lane = tid & 31;
    const int wid  = tid >> 5;
    const int warp_m = wid >> 2;
    const int warp_n = wid & 3;
    const int bm = blockIdx.y * 128;
    const int bn = blockIdx.x * 128;

    const uint32_t a_row = warp_m * 64 + (lane & 15);
    const uint32_t a_kb  = (uint32_t)(lane >> 4) << 4;
    const uint32_t b_row = warp_n * 32 + (lane & 7) + (((uint32_t)lane >> 4) << 3);
    const uint32_t b_kb  = (((uint32_t)lane >> 3) & 1) << 4;

    float acc[4][4][4];
#pragma unroll
    for (int mt = 0; mt < 4; mt++)
#pragma unroll
        for (int nt = 0; nt < 4; nt++)
#pragma unroll
            for (int r = 0; r < 4; r++) acc[mt][nt][r] = 0.0f;

    const int nchunks = K >> 6;              // BK = 64
    load_chunk(Ah, Al, Bh, Bl, bm, bn, K, 0, data0, tid);

    // double-buffered fragments (slot = ks & 1)
    uint32_t afh[2][4][4], afl[2][4][4], bfh[2][2][4], bfl[2][2][4];

    for (int c = 0; c < nchunks; c++) {
        if (c + 1 < nchunks) {
            load_chunk(Ah, Al, Bh, Bl, bm, bn, K, (c + 1) << 6,
                       data0 + ((c + 1) & 1) * 65536, tid);
            asm volatile("cp.async.wait_group 1;" ::: "memory");
        } else {
            asm volatile("cp.async.wait_group 0;" ::: "memory");
        }
        __syncthreads();

        const uint32_t dbase = data0 + (c & 1) * 65536;
        const uint32_t sAh = dbase;
        const uint32_t sAl = dbase + 16384;
        const uint32_t sBh = dbase + 32768;
        const uint32_t sBl = dbase + 49152;

        // fragment loader for one k16 step into slot
#define LOAD_FRAGS(slot, ksi)                                                  \
        do {                                                                   \
            const uint32_t kbyte_ = (uint32_t)(ksi) << 5;                      \
            _Pragma("unroll")                                                  \
            for (int mt = 0; mt < 4; mt++) {                                   \
                const uint32_t off = ((a_row + mt * 16) << 7) + kbyte_ + a_kb; \
                const uint32_t sw = SMEM_SWIZZLE_128B(off);                    \
                ldsm4(afh[slot][mt], sAh + sw);                                \
                ldsm4(afl[slot][mt], sAl + sw);                                \
            }                                                                  \
            _Pragma("unroll")                                                  \
            for (int ng = 0; ng < 2; ng++) {                                   \
                const uint32_t off = ((b_row + ng * 16) << 7) + kbyte_ + b_kb; \
                const uint32_t sw = SMEM_SWIZZLE_128B(off);                    \
                ldsm4(bfh[slot][ng], sBh + sw);                                \
                ldsm4(bfl[slot][ng], sBl + sw);                                \
            }                                                                  \
        } while (0)

        LOAD_FRAGS(0, 0);
#pragma unroll
        for (int ks = 0; ks < 4; ks++) {
            const int cur = ks & 1;
            if (ks < 3) LOAD_FRAGS(cur ^ 1, ks + 1);
#pragma unroll
            for (int mt = 0; mt < 4; mt++) {
#pragma unroll
                for (int nt = 0; nt < 4; nt++) {
                    const int ng = nt >> 1, lo = (nt & 1) * 2;
                    mma16816(acc[mt][nt], afh[cur][mt],
                             bfh[cur][ng][lo], bfh[cur][ng][lo + 1]);
                    mma16816(acc[mt][nt], afh[cur][mt],
                             bfl[cur][ng][lo], bfl[cur][ng][lo + 1]);
                    mma16816(acc[mt][nt], afl[cur][mt],
                             bfh[cur][ng][lo], bfh[cur][ng][lo + 1]);
                }
            }
        }
#undef LOAD_FRAGS
        __syncthreads();
    }

    const int gm0 = bm + warp_m * 64 + (lane >> 2);
    const int gn0 = bn + warp_n * 32 + (lane & 3) * 2;
#pragma unroll
    for (int mt = 0; mt < 4; mt++) {
#pragma unroll
        for (int nt = 0; nt < 4; nt++) {
            const int gm = gm0 + mt * 16;
            const int gn = gn0 + nt * 8;
            const float b0 = bias[gn], b1 = bias[gn + 1];
            float2 v0 = make_float2(acc[mt][nt][0] + b0, acc[mt][nt][1] + b1);
            float2 v1 = make_float2(acc[mt][nt][2] + b0, acc[mt][nt][3] + b1);
            *(float2*)&C[(size_t)gm * N + gn]       = v0;
            *(float2*)&C[(size_t)(gm + 8) * N + gn] = v1;
        }
    }
}

// ---------------------------------------------------------------------------
// RoPE + split qkv -> q/k/v bf16 hi/lo, layout [bh][t][hd]
// ---------------------------------------------------------------------------
__device__ __forceinline__ void st_hl(float v, __nv_bfloat16* hi,
                                      __nv_bfloat16* lo, size_t idx) {
    __nv_bfloat16 h = __float2bfloat16(v);
    hi[idx] = h;
    lo[idx] = __float2bfloat16(v - __bfloat162float(h));
}

__global__ __launch_bounds__(256) void rope_split_hl(
    const float* __restrict__ qkv,
    __nv_bfloat16* __restrict__ qh, __nv_bfloat16* __restrict__ ql,
    __nv_bfloat16* __restrict__ kh, __nv_bfloat16* __restrict__ kl,
    __nv_bfloat16* __restrict__ vh, __nv_bfloat16* __restrict__ vl)
{
    const int idx = blockIdx.x * blockDim.x + threadIdx.x;
    const int i  = idx & 63;
    const int t  = (idx >> 6) & (T_ - 1);
    const int h  = (idx >> 17) & (H_ - 1);
    const int b  = idx >> 21;
    const int bh = idx >> 17;

    const float* src = qkv + ((size_t)(b * T_ + t)) * N1_ + h * (3 * HD_);
    const float q1 = src[i],        q2 = src[64 + i];
    const float k1 = src[128 + i],  k2 = src[192 + i];
    const float v1 = src[256 + i],  v2 = src[320 + i];

    const float theta = powf(10000.0f, -(float)i * (1.0f / 64.0f));
    const float ang = (float)t * theta;
    const float cs = cosf(ang), sn = sinf(ang);

    const size_t dst = ((size_t)bh * T_ + t) * HD_ + i;
    st_hl(q1 * cs - q2 * sn, qh, ql, dst);
    st_hl(q1 * sn + q2 * cs, qh, ql, dst + 64);
    st_hl(k1 * cs - k2 * sn, kh, kl, dst);
    st_hl(k1 * sn + k2 * cs, kh, kl, dst + 64);
    st_hl(v1, vh, vl, dst);
    st_hl(v2, vh, vl, dst + 64);
}

// ---------------------------------------------------------------------------
// Causal flash attention on mma.sync bf16 (3-term splits).
// (unchanged from R7 passing version)
// ---------------------------------------------------------------------------
#define FL_SMEM_BYTES 208896
#define FL_STRIDE 272

__device__ __forceinline__ void fl_load_kv(
    const __nv_bfloat16* Kh, const __nv_bfloat16* Kl,
    const __nv_bfloat16* Vh, const __nv_bfloat16* Vl,
    size_t goff, uint32_t sbuf, int tid)
{
#pragma unroll
    for (int i = 0; i < 16; i++) {
        const int idx = tid + i * 256;
        const int arr = idx >> 10;          // 0:Kh 1:Kl 2:Vh 3:Vl
        const int r   = (idx >> 4) & 63;
        const int seg = idx & 15;
        const __nv_bfloat16* p = (arr == 0) ? Kh : (arr == 1) ? Kl
                               : (arr == 2) ? Vh : Vl;
        const char* src = (const char*)p + ((goff + (size_t)r * HD_) << 1) + (seg << 4);
        const uint32_t dst = sbuf + arr * 17408 + r * FL_STRIDE + (seg << 4);
        CP_ASYNC16(dst, src);
    }
    CP_ASYNC_COMMIT();
}

__global__ __launch_bounds__(256, 1) void flash_hmma(
    const __nv_bfloat16* __restrict__ Qh, const __nv_bfloat16* __restrict__ Ql,
    const __nv_bfloat16* __restrict__ Kh, const __nv_bfloat16* __restrict__ Kl,
    const __nv_bfloat16* __restrict__ Vh, const __nv_bfloat16* __restrict__ Vl,
    __nv_bfloat16* __restrict__ Oh, __nv_bfloat16* __restrict__ Ol)
{
    extern __shared__ __align__(16) char smc[];
    const uint32_t sb  = smem_to_u32(smc);
    const uint32_t sQh = sb, sQl = sb + 34816;
    const uint32_t sKV = sb + 69632;            // + buf*69632

    const int tid  = threadIdx.x;
    const int lane = tid & 31;
    const int warp = tid >> 5;
    const int qt = 15 - (int)blockIdx.x;        // heavy blocks first
    const int bh = blockIdx.y;
    const int b = bh >> 4, h = bh & 15;
    const size_t gbase = (size_t)bh * T_ * HD_;

    // Q load (hi + lo)
    {
        const size_t qoff = gbase + (size_t)qt * 128 * HD_;
#pragma unroll
        for (int i = 0; i < 16; i++) {
            const int idx = tid + i * 256;
            const int arr = idx >> 11;
            const int r   = (idx >> 4) & 127;
            const int seg = idx & 15;
            const char* src = (const char*)(arr ? Ql : Qh) +
                ((qoff + (size_t)r * HD_) << 1) + (seg << 4);
            const uint32_t dst = (arr ? sQl : sQh) + r * FL_STRIDE + (seg << 4);
            CP_ASYNC16(dst, src);
        }
        CP_ASYNC_COMMIT();
    }
    // first KV tile
    fl_load_kv(Kh, Kl, Vh, Vl, gbase, sKV, tid);

    const int r0w = warp * 16;
    const uint32_t aoff = (r0w + (lane & 15)) * FL_STRIDE + ((lane >> 4) << 4);
    const uint32_t boff = ((lane & 7) + ((lane >> 4) << 3)) * FL_STRIDE +
                          (((lane >> 3) & 1) << 4);
    const uint32_t vrow = (lane & 7) + (((lane >> 3) & 1) << 3);
    const uint32_t vcol = (lane >> 4) << 4;

    float o[16][4];
#pragma unroll
    for (int nt = 0; nt < 16; nt++)
#pragma unroll
        for (int r = 0; r < 4; r++) o[nt][r] = 0.0f;
    float m_[2] = {-1e30f, -1e30f};
    float l_[2] = {0.0f, 0.0f};

    const int ktmax = 2 * qt + 1;
    for (int kt = 0; kt <= ktmax; kt++) {
        if (kt > 0) __syncthreads();
        if (kt < ktmax) {
            fl_load_kv(Kh, Kl, Vh, Vl, gbase + (size_t)(kt + 1) * 64 * HD_,
                       sKV + ((kt + 1) & 1) * 69632, tid);
            asm volatile("cp.async.wait_group 1;" ::: "memory");
        } else {
            asm volatile("cp.async.wait_group 0;" ::: "memory");
        }
        __syncthreads();

        const uint32_t kb = sKV + (kt & 1) * 69632;
        const uint32_t sKh = kb, sKl = kb + 17408;
        const uint32_t sVh = kb + 34816, sVl = kb + 52224;

        // ---- S = Q K^T (3-term) ----
        float s[8][4];
#pragma unroll
        for (int nt = 0; nt < 8; nt++)
#pragma unroll
            for (int r = 0; r < 4; r++) s[nt][r] = 0.0f;

#pragma unroll
        for (int ks = 0; ks < 8; ks++) {
            const uint32_t kbyte = (uint32_t)ks << 5;
            uint32_t ah_[4], al_[4];
            ldsm4(ah_, sQh + aoff + kbyte);
            ldsm4(al_, sQl + aoff + kbyte);
            uint32_t bh_[4][4], bl_[4][4];
#pragma unroll
            for (int np = 0; np < 4; np++) {
                const uint32_t off = boff + np * 16 * FL_STRIDE + kbyte;
                ldsm4(bh_[np], sKh + off);
                ldsm4(bl_[np], sKl + off);
            }
#pragma unroll
            for (int nt = 0; nt < 8; nt++) {
                const int ng = nt >> 1, lo = (nt & 1) * 2;
                mma16816(s[nt], ah_, bh_[ng][lo], bh_[ng][lo + 1]);
                mma16816(s[nt], ah_, bl_[ng][lo], bl_[ng][lo + 1]);
                mma16816(s[nt], al_, bh_[ng][lo], bh_[ng][lo + 1]);
            }
        }

        // ---- scale + mask + online softmax ----
        const int qa = qt * 128 + r0w + (lane >> 2);
        const int qb = qa + 8;
        const bool dg = (kt >= 2 * qt);
#pragma unroll
        for (int nt = 0; nt < 8; nt++) {
            const int c0 = kt * 64 + nt * 8 + (lane & 3) * 2;
            s[nt][0] *= SCALE_; s[nt][1] *= SCALE_;
            s[nt][2] *= SCALE_; s[nt][3] *= SCALE_;
            if (dg) {
                if (c0     > qa) s[nt][0] = -1e30f;
                if (c0 + 1 > qa) s[nt][1] = -1e30f;
                if (c0     > qb) s[nt][2] = -1e30f;
                if (c0 + 1 > qb) s[nt][3] = -1e30f;
            }
        }
        float ma = -1e30f, mb = -1e30f;
#pragma unroll
        for (int nt = 0; nt < 8; nt++) {
            ma = fmaxf(ma, fmaxf(s[nt][0], s[nt][1]));
            mb = fmaxf(mb, fmaxf(s[nt][2], s[nt][3]));
        }
        ma = fmaxf(ma, __shfl_xor_sync(0xFFFFFFFF, ma, 1));
        ma = fmaxf(ma, __shfl_xor_sync(0xFFFFFFFF, ma, 2));
        mb = fmaxf(mb, __shfl_xor_sync(0xFFFFFFFF, mb, 1));
        mb = fmaxf(mb, __shfl_xor_sync(0xFFFFFFFF, mb, 2));
        const float mna = fmaxf(m_[0], ma), mnb = fmaxf(m_[1], mb);
        const float ca = __expf(m_[0] - mna), cb = __expf(m_[1] - mnb);
        float suma = 0.0f, sumb = 0.0f;
#pragma unroll
        for (int nt = 0; nt < 8; nt++) {
            s[nt][0] = __expf(s[nt][0] - mna); suma += s[nt][0];
            s[nt][1] = __expf(s[nt][1] - mna); suma += s[nt][1];
            s[nt][2] = __expf(s[nt][2] - mnb); sumb += s[nt][2];
            s[nt][3] = __expf(s[nt][3] - mnb); sumb += s[nt][3];
        }
        suma += __shfl_xor_sync(0xFFFFFFFF, suma, 1);
        suma += __shfl_xor_sync(0xFFFFFFFF, suma, 2);
        sumb += __shfl_xor_sync(0xFFFFFFFF, sumb, 1);
        sumb += __shfl_xor_sync(0xFFFFFFFF, sumb, 2);
        l_[0] = l_[0] * ca + suma;  m_[0] = mna;
        l_[1] = l_[1] * cb + sumb;  m_[1] = mnb;
#pragma unroll
        for (int nt = 0; nt < 16; nt++) {
            o[nt][0] *= ca; o[nt][1] *= ca;
            o[nt][2] *= cb; o[nt][3] *= cb;
        }

        // ---- P fragments (bf16 hi/lo) ----
        uint32_t pa_h[4][4], pa_l[4][4];
#pragma unroll
        for (int j = 0; j < 4; j++) {
            pack_hl(s[2 * j][0],     s[2 * j][1],     pa_h[j][0], pa_l[j][0]);
            pack_hl(s[2 * j][2],     s[2 * j][3],     pa_h[j][1], pa_l[j][1]);
            pack_hl(s[2 * j + 1][0], s[2 * j + 1][1], pa_h[j][2], pa_l[j][2]);
            pack_hl(s[2 * j + 1][2], s[2 * j + 1][3], pa_h[j][3], pa_l[j][3]);
        }

        // ---- O += P V (3-term), V via ldmatrix.trans ----
#pragma unroll
        for (int j = 0; j < 4; j++) {
            const uint32_t rbase = (j * 16 + vrow) * FL_STRIDE + vcol;
#pragma unroll
            for (int dp = 0; dp < 8; dp++) {
                uint32_t vh_[4], vl_[4];
                const uint32_t off = rbase + dp * 32;
                ldsm4t(vh_, sVh + off);
                ldsm4t(vl_, sVl + off);
                const int nt0 = dp * 2, nt1 = nt0 + 1;
                mma16816(o[nt0], pa_h[j], vh_[0], vh_[1]);
                mma16816(o[nt0], pa_l[j], vh_[0], vh_[1]);
                mma16816(o[nt0], pa_h[j], vl_[0], vl_[1]);
                mma16816(o[nt1], pa_h[j], vh_[2], vh_[3]);
                mma16816(o[nt1], pa_l[j], vh_[2], vh_[3]);
                mma16816(o[nt1], pa_h[j], vl_[2], vl_[3]);
            }
        }
    }

    // ---- epilogue: normalize, write bf16 hi/lo to [B*T][D] ----
    const float inva = 1.0f / l_[0], invb = 1.0f / l_[1];
    const int ta = qt * 128 + r0w + (lane >> 2);
    const size_t rowa = (size_t)(b * T_ + ta) * D_;
    const size_t rowb = rowa + 8 * D_;
    const int cb0 = h * HD_ + (lane & 3) * 2;
#pragma unroll
    for (int nt = 0; nt < 16; nt++) {
        const size_t ia = rowa + cb0 + nt * 8;
        const size_t ib = rowb + cb0 + nt * 8;
        uint32_t hA, lA, hB, lB;
        pack_hl(o[nt][0] * inva, o[nt][1] * inva, hA, lA);
        pack_hl(o[nt][2] * invb, o[nt][3] * invb, hB, lB);
        *(uint32_t*)(Oh + ia) = hA;  *(uint32_t*)(Ol + ia) = lA;
        *(uint32_t*)(Oh + ib) = hB;  *(uint32_t*)(Ol + ib) = lB;
    }
}

// ---------------------------------------------------------------------------
// kernel_launch
// ---------------------------------------------------------------------------
extern "C" void kernel_launch(void* const* d_in, const int* in_sizes, int n_in,
                              void* d_out, int out_size)
{
    const float* x     = (const float*)d_in[0];
    const float* w_qkv = (const float*)d_in[1];
    const float* b_qkv = (const float*)d_in[2];
    const float* w_out = (const float*)d_in[3];
    const float* b_out = (const float*)d_in[4];
    float* out = (float*)d_out;

    float* qkv;
    cudaGetSymbolAddress((void**)&qkv, g_qkv);
    __nv_bfloat16 *xh, *xl, *wqh, *wql, *ah, *al, *wh, *wl;
    __nv_bfloat16 *qh, *ql, *kh, *kl, *vh, *vl;
    cudaGetSymbolAddress((void**)&xh,  g_xh);
    cudaGetSymbolAddress((void**)&xl,  g_xl);
    cudaGetSymbolAddress((void**)&wqh, g_wqh);
    cudaGetSymbolAddress((void**)&wql, g_wql);
    cudaGetSymbolAddress((void**)&ah,  g_ah);
    cudaGetSymbolAddress((void**)&al,  g_al);
    cudaGetSymbolAddress((void**)&wh,  g_wh);
    cudaGetSymbolAddress((void**)&wl,  g_wl);
    cudaGetSymbolAddress((void**)&qh,  g_qh);
    cudaGetSymbolAddress((void**)&ql,  g_ql);
    cudaGetSymbolAddress((void**)&kh,  g_kh);
    cudaGetSymbolAddress((void**)&kl,  g_kl);
    cudaGetSymbolAddress((void**)&vh,  g_vh);
    cudaGetSymbolAddress((void**)&vl,  g_vl);

    cudaFuncSetAttribute(gemm_hmma,
                         cudaFuncAttributeMaxDynamicSharedMemorySize,
                         GEMM_SMEM_BYTES);
    cudaFuncSetAttribute(flash_hmma,
                         cudaFuncAttributeMaxDynamicSharedMemorySize,
                         FL_SMEM_BYTES);

    // 0) split x / w_qkv into bf16 hi/lo
    split_bf16<<<((size_t)M_ * D_) / 1024, 256>>>(x, xh, xl);
    split_bf16<<<((size_t)N1_ * D_) / 1024, 256>>>(w_qkv, wqh, wql);
    // 1) qkv = x @ w_qkv^T + b_qkv   (HMMA)
    gemm_hmma<<<dim3(N1_ / 128, M_ / 128), 256, GEMM_SMEM_BYTES>>>(
        xh, xl, wqh, wql, b_qkv, qkv, M_, N1_, D_);
    // 2) RoPE + head split -> bf16 hi/lo
    rope_split_hl<<<(B_ * H_ * T_ * 64) / 256, 256>>>(qkv, qh, ql, kh, kl, vh, vl);
    // 3) causal flash attention (HMMA) -> attn bf16 hi/lo directly
    flash_hmma<<<dim3(16, B_ * H_), 256, FL_SMEM_BYTES>>>(
        qh, ql, kh, kl, vh, vl, ah, al);
    // 4) out = attn @ w_out^T + b_out  (HMMA)
    split_bf16<<<((size_t)D_ * D_) / 1024, 256>>>(w_out, wh, wl);
    gemm_hmma<<<dim3(D_ / 128, M_ / 128), 256, GEMM_SMEM_BYTES>>>(
        ah, al, wh, wl, b_out, out, M_, D_, D_);
}

// round 13
// speedup vs baseline: 1.8837x; 1.2436x over previous
#include <cuda_runtime.h>
#include <cuda_bf16.h>
#include <cuda_fp16.h>
#include <cstdint>
#include <math.h>

// Problem constants (fixed shapes)
#define B_   2
#define T_   2048
#define D_   2048
#define H_   16
#define HD_  128
#define M_   (B_ * T_)      // 4096 rows
#define N1_  (3 * D_)       // 6144 qkv cols
#define SCALE_ 0.022097086912079612f   // 2048^-0.5  (D, not head_dim!)

// ---------------------------------------------------------------------------
// Scratch (device globals — no allocation allowed)
// ---------------------------------------------------------------------------
__device__ float g_qkv[(size_t)M_ * N1_];          // 100.7 MB
// fp16 GEMM operands (A split hi/lo, W single)
__device__ __half g_xh[(size_t)M_ * D_];
__device__ __half g_xl[(size_t)M_ * D_];
__device__ __half g_wq16[(size_t)N1_ * D_];
__device__ __half g_ah[(size_t)M_ * D_];
__device__ __half g_al[(size_t)M_ * D_];
__device__ __half g_wo16[(size_t)D_ * D_];
// roped q/k and v, bf16 hi/lo (flash stays 3-term bf16), layout [bh][t][hd]
#define QKV_ELEMS ((size_t)B_ * H_ * T_ * HD_)
__device__ __nv_bfloat16 g_qh[QKV_ELEMS];
__device__ __nv_bfloat16 g_ql[QKV_ELEMS];
__device__ __nv_bfloat16 g_kh[QKV_ELEMS];
__device__ __nv_bfloat16 g_kl[QKV_ELEMS];
__device__ __nv_bfloat16 g_vh[QKV_ELEMS];
__device__ __nv_bfloat16 g_vl[QKV_ELEMS];

// ---------------------------------------------------------------------------
// PTX helpers (family-portable: ldmatrix / mma.sync / cp.async)
// ---------------------------------------------------------------------------
__device__ __forceinline__ uint32_t smem_to_u32(const void* p) {
    uint32_t a;
    asm("{ .reg .u64 t; cvta.to.shared.u64 t, %1; cvt.u32.u64 %0, t; }"
        : "=r"(a) : "l"(p));
    return a;
}
#define SMEM_SWIZZLE_128B(off) ((off) ^ (((off) >> 3) & 0x70))

#define CP_ASYNC16(dst, src) \
    asm volatile("cp.async.cg.shared.global [%0], [%1], 16;" \
                 :: "r"((uint32_t)(dst)), "l"(src))
#define CP_ASYNC_COMMIT() asm volatile("cp.async.commit_group;" ::: "memory")

__device__ __forceinline__ void ldsm4(uint32_t* r, uint32_t addr) {
    asm volatile("ldmatrix.sync.aligned.m8n8.x4.shared.b16 {%0,%1,%2,%3}, [%4];"
                 : "=r"(r[0]), "=r"(r[1]), "=r"(r[2]), "=r"(r[3]) : "r"(addr));
}
__device__ __forceinline__ void ldsm4t(uint32_t* r, uint32_t addr) {
    asm volatile("ldmatrix.sync.aligned.m8n8.x4.trans.shared.b16 {%0,%1,%2,%3}, [%4];"
                 : "=r"(r[0]), "=r"(r[1]), "=r"(r[2]), "=r"(r[3]) : "r"(addr));
}

// bf16 mma (flash)
__device__ __forceinline__ void mma16816(float* c, const uint32_t* a,
                                         uint32_t b0, uint32_t b1) {
    asm volatile(
        "mma.sync.aligned.m16n8k16.row.col.f32.bf16.bf16.f32 "
        "{%0,%1,%2,%3}, {%4,%5,%6,%7}, {%8,%9}, {%0,%1,%2,%3};"
        : "+f"(c[0]), "+f"(c[1]), "+f"(c[2]), "+f"(c[3])
        : "r"(a[0]), "r"(a[1]), "r"(a[2]), "r"(a[3]), "r"(b0), "r"(b1));
}
// fp16 mma (GEMMs)
__device__ __forceinline__ void mma16816f(float* c, const uint32_t* a,
                                          uint32_t b0, uint32_t b1) {
    asm volatile(
        "mma.sync.aligned.m16n8k16.row.col.f32.f16.f16.f32 "
        "{%0,%1,%2,%3}, {%4,%5,%6,%7}, {%8,%9}, {%0,%1,%2,%3};"
        : "+f"(c[0]), "+f"(c[1]), "+f"(c[2]), "+f"(c[3])
        : "r"(a[0]), "r"(a[1]), "r"(a[2]), "r"(a[3]), "r"(b0), "r"(b1));
}

__device__ __forceinline__ void pack_hl(float p0, float p1,
                                        uint32_t& h, uint32_t& l) {
    __nv_bfloat162 hh = __floats2bfloat162_rn(p0, p1);
    float r0 = p0 - __bfloat162float(hh.x);
    float r1 = p1 - __bfloat162float(hh.y);
    __nv_bfloat162 ll = __floats2bfloat162_rn(r0, r1);
    h = *(uint32_t*)&hh;
    l = *(uint32_t*)&ll;
}
__device__ __forceinline__ void pack_hl16(float p0, float p1,
                                          uint32_t& h, uint32_t& l) {
    __half2 hh = __floats2half2_rn(p0, p1);
    float r0 = p0 - __half2float(__low2half(hh));
    float r1 = p1 - __half2float(__high2half(hh));
    __half2 ll = __floats2half2_rn(r0, r1);
    h = *(uint32_t*)&hh;
    l = *(uint32_t*)&ll;
}

// ---------------------------------------------------------------------------
// fp32 -> (fp16 hi, fp16 lo) split  /  fp32 -> fp16 convert
// ---------------------------------------------------------------------------
__global__ __launch_bounds__(256) void split_fp16(
    const float* __restrict__ src, __half* __restrict__ hi,
    __half* __restrict__ lo)
{
    const int i = blockIdx.x * 256 + threadIdx.x;   // float4 index
    float4 v = ((const float4*)src)[i];
    uint32_t h0, l0, h1, l1;
    pack_hl16(v.x, v.y, h0, l0);
    pack_hl16(v.z, v.w, h1, l1);
    ((uint2*)hi)[i] = make_uint2(h0, h1);
    ((uint2*)lo)[i] = make_uint2(l0, l1);
}

__global__ __launch_bounds__(256) void conv_fp16(
    const float* __restrict__ src, __half* __restrict__ dst)
{
    const int i = blockIdx.x * 256 + threadIdx.x;   // float4 index
    float4 v = ((const float4*)src)[i];
    __half2 a = __floats2half2_rn(v.x, v.y);
    __half2 b = __floats2half2_rn(v.z, v.w);
    ((uint2*)dst)[i] = make_uint2(*(uint32_t*)&a, *(uint32_t*)&b);
}

// ---------------------------------------------------------------------------
// fp16 HMMA GEMM: C[M,N] = (Ah+Al)[M,K] @ W16[N,K]^T + bias
// A split into fp16 hi/lo (22-bit effective), W single fp16.
// 2 MMAs per (mt,nt) per k16 — 2/3 the MMA count of the bf16 3-term version.
// CTA 128x128, BK=64, 8 warps (2m x 4n), warp tile 64x32.
// SMEM per buffer (48KB): Ah 16K | Al 16K | B 16K; 128B rows, SW128. 2 bufs.
// ---------------------------------------------------------------------------
#define GEMM_SMEM_BYTES (2 * 49152 + 1024)

__device__ __forceinline__ void load_chunk3(
    const __half* Ah, const __half* Al, const __half* Bw,
    int bm, int bn, int K, int k0, uint32_t dbase, int tid)
{
#pragma unroll
    for (int i = 0; i < 12; i++) {
        const int idx = tid + i * 256;
        const int t   = idx >> 10;           // tile 0..2
        const int r   = (idx >> 3) & 127;    // row within tile
        const int c16 = idx & 7;             // 16B segment within 128B row
        const __half* sp;
        int row;
        if (t == 0)      { sp = Ah; row = bm + r; }
        else if (t == 1) { sp = Al; row = bm + r; }
        else             { sp = Bw; row = bn + r; }
        const char* src = (const char*)sp +
            (((size_t)row * K + k0) << 1) + (c16 << 4);
        const uint32_t off = (r << 7) + (c16 << 4);
        const uint32_t dst = dbase + (t << 14) + SMEM_SWIZZLE_128B(off);
        CP_ASYNC16(dst, src);
    }
    CP_ASYNC_COMMIT();
}

__global__ __launch_bounds__(256, 1) void gemm_hmma16(
    const __half* __restrict__ Ah, const __half* __restrict__ Al,
    const __half* __restrict__ Bw,
    const float* __restrict__ bias, float* __restrict__ C,
    int M, int N, int K)
{
    extern __shared__ __align__(16) char smem[];
    const uint32_t data0 = (smem_to_u32(smem) + 1023) & ~1023u;

    const int tid  = threadIdx.x;
    const int lane = tid & 31;
    const int wid  = tid >> 5;
    const int warp_m = wid >> 2;
    const int warp_n = wid & 3;
    const int bm = blockIdx.y * 128;
    const int bn = blockIdx.x * 128;

    const uint32_t a_row = warp_m * 64 + (lane & 15);
    const uint32_t a_kb  = (uint32_t)(lane >> 4) << 4;
    const uint32_t b_row = warp_n * 32 + (lane & 7) + (((uint32_t)lane >> 4) << 3);
    const uint32_t b_kb  = (((uint32_t)lane >> 3) & 1) << 4;

    float acc[4][4][4];
#pragma unroll
    for (int mt = 0; mt < 4; mt++)
#pragma unroll
        for (int nt = 0; nt < 4; nt++)
#pragma unroll
            for (int r = 0; r < 4; r++) acc[mt][nt][r] = 0.0f;

    const int nchunks = K >> 6;              // BK = 64
    load_chunk3(Ah, Al, Bw, bm, bn, K, 0, data0, tid);

    for (int c = 0; c < nchunks; c++) {
        if (c + 1 < nchunks) {
            load_chunk3(Ah, Al, Bw, bm, bn, K, (c + 1) << 6,
                        data0 + ((c + 1) & 1) * 49152, tid);
            asm volatile("cp.async.wait_group 1;" ::: "memory");
        } else {
            asm volatile("cp.async.wait_group 0;" ::: "memory");
        }
        __syncthreads();

        const uint32_t dbase = data0 + (c & 1) * 49152;
        const uint32_t sAh = dbase;
        const uint32_t sAl = dbase + 16384;
        const uint32_t sB  = dbase + 32768;

#pragma unroll
        for (int ks = 0; ks < 4; ks++) {
            const uint32_t kbyte = (uint32_t)ks << 5;   // 32B per k16 step

            uint32_t af_h[4][4], af_l[4][4];
#pragma unroll
            for (int mt = 0; mt < 4; mt++) {
                const uint32_t off = ((a_row + mt * 16) << 7) + kbyte + a_kb;
                const uint32_t sw = SMEM_SWIZZLE_128B(off);
                ldsm4(af_h[mt], sAh + sw);
                ldsm4(af_l[mt], sAl + sw);
            }
            uint32_t bf_[2][4];
#pragma unroll
            for (int ng = 0; ng < 2; ng++) {
                const uint32_t off = ((b_row + ng * 16) << 7) + kbyte + b_kb;
                const uint32_t sw = SMEM_SWIZZLE_128B(off);
                ldsm4(bf_[ng], sB + sw);
            }
#pragma unroll
            for (int mt = 0; mt < 4; mt++) {
#pragma unroll
                for (int nt = 0; nt < 4; nt++) {
                    const int ng = nt >> 1, lo = (nt & 1) * 2;
                    mma16816f(acc[mt][nt], af_h[mt], bf_[ng][lo], bf_[ng][lo + 1]);
                    mma16816f(acc[mt][nt], af_l[mt], bf_[ng][lo], bf_[ng][lo + 1]);
                }
            }
        }
        __syncthreads();
    }

    const int gm0 = bm + warp_m * 64 + (lane >> 2);
    const int gn0 = bn + warp_n * 32 + (lane & 3) * 2;
#pragma unroll
    for (int mt = 0; mt < 4; mt++) {
#pragma unroll
        for (int nt = 0; nt < 4; nt++) {
            const int gm = gm0 + mt * 16;
            const int gn = gn0 + nt * 8;
            const float b0 = bias[gn], b1 = bias[gn + 1];
            float2 v0 = make_float2(acc[mt][nt][0] + b0, acc[mt][nt][1] + b1);
            float2 v1 = make_float2(acc[mt][nt][2] + b0, acc[mt][nt][3] + b1);
            *(float2*)&C[(size_t)gm * N + gn]       = v0;
            *(float2*)&C[(size_t)(gm + 8) * N + gn] = v1;
        }
    }
}

// ---------------------------------------------------------------------------
// RoPE + split qkv -> q/k/v bf16 hi/lo, layout [bh][t][hd]
// ---------------------------------------------------------------------------
__device__ __forceinline__ void st_hl(float v, __nv_bfloat16* hi,
                                      __nv_bfloat16* lo, size_t idx) {
    __nv_bfloat16 h = __float2bfloat16(v);
    hi[idx] = h;
    lo[idx] = __float2bfloat16(v - __bfloat162float(h));
}

__global__ __launch_bounds__(256) void rope_split_hl(
    const float* __restrict__ qkv,
    __nv_bfloat16* __restrict__ qh, __nv_bfloat16* __restrict__ ql,
    __nv_bfloat16* __restrict__ kh, __nv_bfloat16* __restrict__ kl,
    __nv_bfloat16* __restrict__ vh, __nv_bfloat16* __restrict__ vl)
{
    const int idx = blockIdx.x * blockDim.x + threadIdx.x;
    const int i  = idx & 63;
    const int t  = (idx >> 6) & (T_ - 1);
    const int h  = (idx >> 17) & (H_ - 1);
    const int b  = idx >> 21;
    const int bh = idx >> 17;

    const float* src = qkv + ((size_t)(b * T_ + t)) * N1_ + h * (3 * HD_);
    const float q1 = src[i],        q2 = src[64 + i];
    const float k1 = src[128 + i],  k2 = src[192 + i];
    const float v1 = src[256 + i],  v2 = src[320 + i];

    const float theta = powf(10000.0f, -(float)i * (1.0f / 64.0f));
    const float ang = (float)t * theta;
    const float cs = cosf(ang), sn = sinf(ang);

    const size_t dst = ((size_t)bh * T_ + t) * HD_ + i;
    st_hl(q1 * cs - q2 * sn, qh, ql, dst);
    st_hl(q1 * sn + q2 * cs, qh, ql, dst + 64);
    st_hl(k1 * cs - k2 * sn, kh, kl, dst);
    st_hl(k1 * sn + k2 * cs, kh, kl, dst + 64);
    st_hl(v1, vh, vl, dst);
    st_hl(v2, vh, vl, dst + 64);
}

// ---------------------------------------------------------------------------
// Causal flash attention on mma.sync bf16 (3-term splits).
// Internals unchanged from R7 passing version; epilogue now emits fp16 hi/lo
// (for the fp16 output GEMM).
// ---------------------------------------------------------------------------
#define FL_SMEM_BYTES 208896
#define FL_STRIDE 272

__device__ __forceinline__ void fl_load_kv(
    const __nv_bfloat16* Kh, const __nv_bfloat16* Kl,
    const __nv_bfloat16* Vh, const __nv_bfloat16* Vl,
    size_t goff, uint32_t sbuf, int tid)
{
#pragma unroll
    for (int i = 0; i < 16; i++) {
        const int idx = tid + i * 256;
        const int arr = idx >> 10;          // 0:Kh 1:Kl 2:Vh 3:Vl
        const int r   = (idx >> 4) & 63;
        const int seg = idx & 15;
        const __nv_bfloat16* p = (arr == 0) ? Kh : (arr == 1) ? Kl
                               : (arr == 2) ? Vh : Vl;
        const char* src = (const char*)p + ((goff + (size_t)r * HD_) << 1) + (seg << 4);
        const uint32_t dst = sbuf + arr * 17408 + r * FL_STRIDE + (seg << 4);
        CP_ASYNC16(dst, src);
    }
    CP_ASYNC_COMMIT();
}

__global__ __launch_bounds__(256, 1) void flash_hmma(
    const __nv_bfloat16* __restrict__ Qh, const __nv_bfloat16* __restrict__ Ql,
    const __nv_bfloat16* __restrict__ Kh, const __nv_bfloat16* __restrict__ Kl,
    const __nv_bfloat16* __restrict__ Vh, const __nv_bfloat16* __restrict__ Vl,
    __half* __restrict__ Oh, __half* __restrict__ Ol)
{
    extern __shared__ __align__(16) char smc[];
    const uint32_t sb  = smem_to_u32(smc);
    const uint32_t sQh = sb, sQl = sb + 34816;
    const uint32_t sKV = sb + 69632;            // + buf*69632

    const int tid  = threadIdx.x;
    const int lane = tid & 31;
    const int warp = tid >> 5;
    const int qt = 15 - (int)blockIdx.x;        // heavy blocks first
    const int bh = blockIdx.y;
    const int b = bh >> 4, h = bh & 15;
    const size_t gbase = (size_t)bh * T_ * HD_;

    // Q load (hi + lo)
    {
        const size_t qoff = gbase + (size_t)qt * 128 * HD_;
#pragma unroll
        for (int i = 0; i < 16; i++) {
            const int idx = tid + i * 256;
            const int arr = idx >> 11;
            const int r   = (idx >> 4) & 127;
            const int seg = idx & 15;
            const char* src = (const char*)(arr ? Ql : Qh) +
                ((qoff + (size_t)r * HD_) << 1) + (seg << 4);
            const uint32_t dst = (arr ? sQl : sQh) + r * FL_STRIDE + (seg << 4);
            CP_ASYNC16(dst, src);
        }
        CP_ASYNC_COMMIT();
    }
    // first KV tile
    fl_load_kv(Kh, Kl, Vh, Vl, gbase, sKV, tid);

    const int r0w = warp * 16;
    const uint32_t aoff = (r0w + (lane & 15)) * FL_STRIDE + ((lane >> 4) << 4);
    const uint32_t boff = ((lane & 7) + ((lane >> 4) << 3)) * FL_STRIDE +
                          (((lane >> 3) & 1) << 4);
    const uint32_t vrow = (lane & 7) + (((lane >> 3) & 1) << 3);
    const uint32_t vcol = (lane >> 4) << 4;

    float o[16][4];
#pragma unroll
    for (int nt = 0; nt < 16; nt++)
#pragma unroll
        for (int r = 0; r < 4; r++) o[nt][r] = 0.0f;
    float m_[2] = {-1e30f, -1e30f};
    float l_[2] = {0.0f, 0.0f};

    const int ktmax = 2 * qt + 1;
    for (int kt = 0; kt <= ktmax; kt++) {
        if (kt > 0) __syncthreads();
        if (kt < ktmax) {
            fl_load_kv(Kh, Kl, Vh, Vl, gbase + (size_t)(kt + 1) * 64 * HD_,
                       sKV + ((kt + 1) & 1) * 69632, tid);
            asm volatile("cp.async.wait_group 1;" ::: "memory");
        } else {
            asm volatile("cp.async.wait_group 0;" ::: "memory");
        }
        __syncthreads();

        const uint32_t kb = sKV + (kt & 1) * 69632;
        const uint32_t sKh = kb, sKl = kb + 17408;
        const uint32_t sVh = kb + 34816, sVl = kb + 52224;

        // ---- S = Q K^T (3-term) ----
        float s[8][4];
#pragma unroll
        for (int nt = 0; nt < 8; nt++)
#pragma unroll
            for (int r = 0; r < 4; r++) s[nt][r] = 0.0f;

#pragma unroll
        for (int ks = 0; ks < 8; ks++) {
            const uint32_t kbyte = (uint32_t)ks << 5;
            uint32_t ah_[4], al_[4];
            ldsm4(ah_, sQh + aoff + kbyte);
            ldsm4(al_, sQl + aoff + kbyte);
            uint32_t bh_[4][4], bl_[4][4];
#pragma unroll
            for (int np = 0; np < 4; np++) {
                const uint32_t off = boff + np * 16 * FL_STRIDE + kbyte;
                ldsm4(bh_[np], sKh + off);
                ldsm4(bl_[np], sKl + off);
            }
#pragma unroll
            for (int nt = 0; nt < 8; nt++) {
                const int ng = nt >> 1, lo = (nt & 1) * 2;
                mma16816(s[nt], ah_, bh_[ng][lo], bh_[ng][lo + 1]);
                mma16816(s[nt], ah_, bl_[ng][lo], bl_[ng][lo + 1]);
                mma16816(s[nt], al_, bh_[ng][lo], bh_[ng][lo + 1]);
            }
        }

        // ---- scale + mask + online softmax ----
        const int qa = qt * 128 + r0w + (lane >> 2);
        const int qb = qa + 8;
        const bool dg = (kt >= 2 * qt);
#pragma unroll
        for (int nt = 0; nt < 8; nt++) {
            const int c0 = kt * 64 + nt * 8 + (lane & 3) * 2;
            s[nt][0] *= SCALE_; s[nt][1] *= SCALE_;
            s[nt][2] *= SCALE_; s[nt][3] *= SCALE_;
            if (dg) {
                if (c0     > qa) s[nt][0] = -1e30f;
                if (c0 + 1 > qa) s[nt][1] = -1e30f;
                if (c0     > qb) s[nt][2] = -1e30f;
                if (c0 + 1 > qb) s[nt][3] = -1e30f;
            }
        }
        float ma = -1e30f, mb = -1e30f;
#pragma unroll
        for (int nt = 0; nt < 8; nt++) {
            ma = fmaxf(ma, fmaxf(s[nt][0], s[nt][1]));
            mb = fmaxf(mb, fmaxf(s[nt][2], s[nt][3]));
        }
        ma = fmaxf(ma, __shfl_xor_sync(0xFFFFFFFF, ma, 1));
        ma = fmaxf(ma, __shfl_xor_sync(0xFFFFFFFF, ma, 2));
        mb = fmaxf(mb, __shfl_xor_sync(0xFFFFFFFF, mb, 1));
        mb = fmaxf(mb, __shfl_xor_sync(0xFFFFFFFF, mb, 2));
        const float mna = fmaxf(m_[0], ma), mnb = fmaxf(m_[1], mb);
        const float ca = __expf(m_[0] - mna), cb = __expf(m_[1] - mnb);
        float suma = 0.0f, sumb = 0.0f;
#pragma unroll
        for (int nt = 0; nt < 8; nt++) {
            s[nt][0] = __expf(s[nt][0] - mna); suma += s[nt][0];
            s[nt][1] = __expf(s[nt][1] - mna); suma += s[nt][1];
            s[nt][2] = __expf(s[nt][2] - mnb); sumb += s[nt][2];
            s[nt][3] = __expf(s[nt][3] - mnb); sumb += s[nt][3];
        }
        suma += __shfl_xor_sync(0xFFFFFFFF, suma, 1);
        suma += __shfl_xor_sync(0xFFFFFFFF, suma, 2);
        sumb += __shfl_xor_sync(0xFFFFFFFF, sumb, 1);
        sumb += __shfl_xor_sync(0xFFFFFFFF, sumb, 2);
        l_[0] = l_[0] * ca + suma;  m_[0] = mna;
        l_[1] = l_[1] * cb + sumb;  m_[1] = mnb;
#pragma unroll
        for (int nt = 0; nt < 16; nt++) {
            o[nt][0] *= ca; o[nt][1] *= ca;
            o[nt][2] *= cb; o[nt][3] *= cb;
        }

        // ---- P fragments (bf16 hi/lo) ----
        uint32_t pa_h[4][4], pa_l[4][4];
#pragma unroll
        for (int j = 0; j < 4; j++) {
            pack_hl(s[2 * j][0],     s[2 * j][1],     pa_h[j][0], pa_l[j][0]);
            pack_hl(s[2 * j][2],     s[2 * j][3],     pa_h[j][1], pa_l[j][1]);
            pack_hl(s[2 * j + 1][0], s[2 * j + 1][1], pa_h[j][2], pa_l[j][2]);
            pack_hl(s[2 * j + 1][2], s[2 * j + 1][3], pa_h[j][3], pa_l[j][3]);
        }

        // ---- O += P V (3-term), V via ldmatrix.trans ----
#pragma unroll
        for (int j = 0; j < 4; j++) {
            const uint32_t rbase = (j * 16 + vrow) * FL_STRIDE + vcol;
#pragma unroll
            for (int dp = 0; dp < 8; dp++) {
                uint32_t vh_[4], vl_[4];
                const uint32_t off = rbase + dp * 32;
                ldsm4t(vh_, sVh + off);
                ldsm4t(vl_, sVl + off);
                const int nt0 = dp * 2, nt1 = nt0 + 1;
                mma16816(o[nt0], pa_h[j], vh_[0], vh_[1]);
                mma16816(o[nt0], pa_l[j], vh_[0], vh_[1]);
                mma16816(o[nt0], pa_h[j], vl_[0], vl_[1]);
                mma16816(o[nt1], pa_h[j], vh_[2], vh_[3]);
                mma16816(o[nt1], pa_l[j], vh_[2], vh_[3]);
                mma16816(o[nt1], pa_h[j], vl_[2], vl_[3]);
            }
        }
    }

    // ---- epilogue: normalize, write fp16 hi/lo to [B*T][D] ----
    const float inva = 1.0f / l_[0], invb = 1.0f / l_[1];
    const int ta = qt * 128 + r0w + (lane >> 2);
    const size_t rowa = (size_t)(b * T_ + ta) * D_;
    const size_t rowb = rowa + 8 * D_;
    const int cb0 = h * HD_ + (lane & 3) * 2;
#pragma unroll
    for (int nt = 0; nt < 16; nt++) {
        const size_t ia = rowa + cb0 + nt * 8;
        const size_t ib = rowb + cb0 + nt * 8;
        uint32_t hA, lA, hB, lB;
        pack_hl16(o[nt][0] * inva, o[nt][1] * inva, hA, lA);
        pack_hl16(o[nt][2] * invb, o[nt][3] * invb, hB, lB);
        *(uint32_t*)(Oh + ia) = hA;  *(uint32_t*)(Ol + ia) = lA;
        *(uint32_t*)(Oh + ib) = hB;  *(uint32_t*)(Ol + ib) = lB;
    }
}

// ---------------------------------------------------------------------------
// kernel_launch
// ---------------------------------------------------------------------------
extern "C" void kernel_launch(void* const* d_in, const int* in_sizes, int n_in,
                              void* d_out, int out_size)
{
    const float* x     = (const float*)d_in[0];
    const float* w_qkv = (const float*)d_in[1];
    const float* b_qkv = (const float*)d_in[2];
    const float* w_out = (const float*)d_in[3];
    const float* b_out = (const float*)d_in[4];
    float* out = (float*)d_out;

    float* qkv;
    cudaGetSymbolAddress((void**)&qkv, g_qkv);
    __half *xh, *xl, *wq16, *ah, *al, *wo16;
    __nv_bfloat16 *qh, *ql, *kh, *kl, *vh, *vl;
    cudaGetSymbolAddress((void**)&xh,   g_xh);
    cudaGetSymbolAddress((void**)&xl,   g_xl);
    cudaGetSymbolAddress((void**)&wq16, g_wq16);
    cudaGetSymbolAddress((void**)&ah,   g_ah);
    cudaGetSymbolAddress((void**)&al,   g_al);
    cudaGetSymbolAddress((void**)&wo16, g_wo16);
    cudaGetSymbolAddress((void**)&qh,   g_qh);
    cudaGetSymbolAddress((void**)&ql,   g_ql);
    cudaGetSymbolAddress((void**)&kh,   g_kh);
    cudaGetSymbolAddress((void**)&kl,   g_kl);
    cudaGetSymbolAddress((void**)&vh,   g_vh);
    cudaGetSymbolAddress((void**)&vl,   g_vl);

    cudaFuncSetAttribute(gemm_hmma16,
                         cudaFuncAttributeMaxDynamicSharedMemorySize,
                         GEMM_SMEM_BYTES);
    cudaFuncSetAttribute(flash_hmma,
                         cudaFuncAttributeMaxDynamicSharedMemorySize,
                         FL_SMEM_BYTES);

    // 0) x -> fp16 hi/lo ; w_qkv -> fp16
    split_fp16<<<((size_t)M_ * D_) / 1024, 256>>>(x, xh, xl);
    conv_fp16<<<((size_t)N1_ * D_) / 1024, 256>>>(w_qkv, wq16);
    // 1) qkv = (xh+xl) @ wq16^T + b_qkv   (fp16 HMMA, 2-term)
    gemm_hmma16<<<dim3(N1_ / 128, M_ / 128), 256, GEMM_SMEM_BYTES>>>(
        xh, xl, wq16, b_qkv, qkv, M_, N1_, D_);
    // 2) RoPE + head split -> bf16 hi/lo (flash stays 3-term bf16)
    rope_split_hl<<<(B_ * H_ * T_ * 64) / 256, 256>>>(qkv, qh, ql, kh, kl, vh, vl);
    // 3) causal flash attention (HMMA) -> attn fp16 hi/lo directly
    flash_hmma<<<dim3(16, B_ * H_), 256, FL_SMEM_BYTES>>>(
        qh, ql, kh, kl, vh, vl, ah, al);
    // 4) w_out -> fp16 ; out = (ah+al) @ wo16^T + b_out  (fp16 HMMA)
    conv_fp16<<<((size_t)D_ * D_) / 1024, 256>>>(w_out, wo16);
    gemm_hmma16<<<dim3(D_ / 128, M_ / 128), 256, GEMM_SMEM_BYTES>>>(
        ah, al, wo16, b_out, out, M_, D_, D_);
}

// round 14
// speedup vs baseline: 2.8743x; 1.5259x over previous
#include <cuda_runtime.h>
#include <cuda_bf16.h>
#include <cuda_fp16.h>
#include <cstdint>
#include <math.h>

// Problem constants (fixed shapes)
#define B_   2
#define T_   2048
#define D_   2048
#define H_   16
#define HD_  128
#define M_   (B_ * T_)      // 4096 rows
#define N1_  (3 * D_)       // 6144 qkv cols
#define SCALE_ 0.022097086912079612f   // 2048^-0.5  (D, not head_dim!)

// ---------------------------------------------------------------------------
// Scratch (device globals — no allocation allowed)
// ---------------------------------------------------------------------------
__device__ float g_qkv[(size_t)M_ * N1_];          // 100.7 MB
__device__ __half g_x16[(size_t)M_ * D_];
__device__ __half g_wq16[(size_t)N1_ * D_];
__device__ __half g_ah[(size_t)M_ * D_];           // attn hi (split for GEMM2)
__device__ __half g_al[(size_t)M_ * D_];           // attn lo
__device__ __half g_wo16[(size_t)D_ * D_];
// roped q/k and v, single fp16, layout [bh][t][hd]
#define QKV_ELEMS ((size_t)B_ * H_ * T_ * HD_)
__device__ __half g_q16[QKV_ELEMS];
__device__ __half g_k16[QKV_ELEMS];
__device__ __half g_v16[QKV_ELEMS];

// ---------------------------------------------------------------------------
// PTX helpers (family-portable: ldmatrix / mma.sync / cp.async)
// ---------------------------------------------------------------------------
__device__ __forceinline__ uint32_t smem_to_u32(const void* p) {
    uint32_t a;
    asm("{ .reg .u64 t; cvta.to.shared.u64 t, %1; cvt.u32.u64 %0, t; }"
        : "=r"(a) : "l"(p));
    return a;
}
#define SMEM_SWIZZLE_128B(off) ((off) ^ (((off) >> 3) & 0x70))

#define CP_ASYNC16(dst, src) \
    asm volatile("cp.async.cg.shared.global [%0], [%1], 16;" \
                 :: "r"((uint32_t)(dst)), "l"(src))
#define CP_ASYNC_COMMIT() asm volatile("cp.async.commit_group;" ::: "memory")

__device__ __forceinline__ void ldsm4(uint32_t* r, uint32_t addr) {
    asm volatile("ldmatrix.sync.aligned.m8n8.x4.shared.b16 {%0,%1,%2,%3}, [%4];"
                 : "=r"(r[0]), "=r"(r[1]), "=r"(r[2]), "=r"(r[3]) : "r"(addr));
}
__device__ __forceinline__ void ldsm4t(uint32_t* r, uint32_t addr) {
    asm volatile("ldmatrix.sync.aligned.m8n8.x4.trans.shared.b16 {%0,%1,%2,%3}, [%4];"
                 : "=r"(r[0]), "=r"(r[1]), "=r"(r[2]), "=r"(r[3]) : "r"(addr));
}

// fp16 mma
__device__ __forceinline__ void mma16816f(float* c, const uint32_t* a,
                                          uint32_t b0, uint32_t b1) {
    asm volatile(
        "mma.sync.aligned.m16n8k16.row.col.f32.f16.f16.f32 "
        "{%0,%1,%2,%3}, {%4,%5,%6,%7}, {%8,%9}, {%0,%1,%2,%3};"
        : "+f"(c[0]), "+f"(c[1]), "+f"(c[2]), "+f"(c[3])
        : "r"(a[0]), "r"(a[1]), "r"(a[2]), "r"(a[3]), "r"(b0), "r"(b1));
}

__device__ __forceinline__ void pack_hl16(float p0, float p1,
                                          uint32_t& h, uint32_t& l) {
    __half2 hh = __floats2half2_rn(p0, p1);
    float r0 = p0 - __half2float(__low2half(hh));
    float r1 = p1 - __half2float(__high2half(hh));
    __half2 ll = __floats2half2_rn(r0, r1);
    h = *(uint32_t*)&hh;
    l = *(uint32_t*)&ll;
}
__device__ __forceinline__ uint32_t pack2h(float p0, float p1) {
    __half2 hh = __floats2half2_rn(p0, p1);
    return *(uint32_t*)&hh;
}

// ---------------------------------------------------------------------------
// fp32 -> (fp16 hi, fp16 lo) split  /  fp32 -> fp16 convert
// ---------------------------------------------------------------------------
__global__ __launch_bounds__(256) void conv_fp16(
    const float* __restrict__ src, __half* __restrict__ dst)
{
    const int i = blockIdx.x * 256 + threadIdx.x;   // float4 index
    float4 v = ((const float4*)src)[i];
    __half2 a = __floats2half2_rn(v.x, v.y);
    __half2 b = __floats2half2_rn(v.z, v.w);
    ((uint2*)dst)[i] = make_uint2(*(uint32_t*)&a, *(uint32_t*)&b);
}

// ---------------------------------------------------------------------------
// GEMM1: single x single fp16.  C[M,N] = A16[M,K] @ W16[N,K]^T + bias
// CTA 128x128, BK=64, 8 warps (2m x 4n). 1 MMA per (mt,nt) per k16.
// SMEM per buffer (32KB): A 16K | B 16K; 128B rows, SW128. 2 buffers.
// ---------------------------------------------------------------------------
#define G1_SMEM_BYTES (2 * 32768 + 1024)

__device__ __forceinline__ void load_chunk2(
    const __half* A, const __half* Bw,
    int bm, int bn, int K, int k0, uint32_t dbase, int tid)
{
#pragma unroll
    for (int i = 0; i < 8; i++) {
        const int idx = tid + i * 256;
        const int t   = idx >> 10;           // 0:A 1:B
        const int r   = (idx >> 3) & 127;
        const int c16 = idx & 7;
        const __half* sp = t ? Bw : A;
        const int row = (t ? bn : bm) + r;
        const char* src = (const char*)sp +
            (((size_t)row * K + k0) << 1) + (c16 << 4);
        const uint32_t off = (r << 7) + (c16 << 4);
        const uint32_t dst = dbase + (t << 14) + SMEM_SWIZZLE_128B(off);
        CP_ASYNC16(dst, src);
    }
    CP_ASYNC_COMMIT();
}

__global__ __launch_bounds__(256, 1) void gemm_ss(
    const __half* __restrict__ A16, const __half* __restrict__ Bw,
    const float* __restrict__ bias, float* __restrict__ C,
    int M, int N, int K)
{
    extern __shared__ __align__(16) char smem[];
    const uint32_t data0 = (smem_to_u32(smem) + 1023) & ~1023u;

    const int tid  = threadIdx.x;
    const int lane = tid & 31;
    const int wid  = tid >> 5;
    const int warp_m = wid >> 2;
    const int warp_n = wid & 3;
    const int bm = blockIdx.y * 128;
    const int bn = blockIdx.x * 128;

    const uint32_t a_row = warp_m * 64 + (lane & 15);
    const uint32_t a_kb  = (uint32_t)(lane >> 4) << 4;
    const uint32_t b_row = warp_n * 32 + (lane & 7) + (((uint32_t)lane >> 4) << 3);
    const uint32_t b_kb  = (((uint32_t)lane >> 3) & 1) << 4;

    float acc[4][4][4];
#pragma unroll
    for (int mt = 0; mt < 4; mt++)
#pragma unroll
        for (int nt = 0; nt < 4; nt++)
#pragma unroll
            for (int r = 0; r < 4; r++) acc[mt][nt][r] = 0.0f;

    const int nchunks = K >> 6;
    load_chunk2(A16, Bw, bm, bn, K, 0, data0, tid);

    for (int c = 0; c < nchunks; c++) {
        if (c + 1 < nchunks) {
            load_chunk2(A16, Bw, bm, bn, K, (c + 1) << 6,
                        data0 + ((c + 1) & 1) * 32768, tid);
            asm volatile("cp.async.wait_group 1;" ::: "memory");
        } else {
            asm volatile("cp.async.wait_group 0;" ::: "memory");
        }
        __syncthreads();

        const uint32_t dbase = data0 + (c & 1) * 32768;
        const uint32_t sA = dbase;
        const uint32_t sB = dbase + 16384;

#pragma unroll
        for (int ks = 0; ks < 4; ks++) {
            const uint32_t kbyte = (uint32_t)ks << 5;

            uint32_t af_[4][4];
#pragma unroll
            for (int mt = 0; mt < 4; mt++) {
                const uint32_t off = ((a_row + mt * 16) << 7) + kbyte + a_kb;
                ldsm4(af_[mt], sA + SMEM_SWIZZLE_128B(off));
            }
            uint32_t bf_[2][4];
#pragma unroll
            for (int ng = 0; ng < 2; ng++) {
                const uint32_t off = ((b_row + ng * 16) << 7) + kbyte + b_kb;
                ldsm4(bf_[ng], sB + SMEM_SWIZZLE_128B(off));
            }
#pragma unroll
            for (int mt = 0; mt < 4; mt++) {
#pragma unroll
                for (int nt = 0; nt < 4; nt++) {
                    const int ng = nt >> 1, lo = (nt & 1) * 2;
                    mma16816f(acc[mt][nt], af_[mt], bf_[ng][lo], bf_[ng][lo + 1]);
                }
            }
        }
        __syncthreads();
    }

    const int gm0 = bm + warp_m * 64 + (lane >> 2);
    const int gn0 = bn + warp_n * 32 + (lane & 3) * 2;
#pragma unroll
    for (int mt = 0; mt < 4; mt++) {
#pragma unroll
        for (int nt = 0; nt < 4; nt++) {
            const int gm = gm0 + mt * 16;
            const int gn = gn0 + nt * 8;
            const float b0 = bias[gn], b1 = bias[gn + 1];
            float2 v0 = make_float2(acc[mt][nt][0] + b0, acc[mt][nt][1] + b1);
            float2 v1 = make_float2(acc[mt][nt][2] + b0, acc[mt][nt][3] + b1);
            *(float2*)&C[(size_t)gm * N + gn]       = v0;
            *(float2*)&C[(size_t)(gm + 8) * N + gn] = v1;
        }
    }
}

// ---------------------------------------------------------------------------
// GEMM2: A split fp16 hi/lo x W single fp16 (2 MMAs per step) — protects
// final output accuracy.  (R13 passing version, unchanged)
// ---------------------------------------------------------------------------
#define G2_SMEM_BYTES (2 * 49152 + 1024)

__device__ __forceinline__ void load_chunk3(
    const __half* Ah, const __half* Al, const __half* Bw,
    int bm, int bn, int K, int k0, uint32_t dbase, int tid)
{
#pragma unroll
    for (int i = 0; i < 12; i++) {
        const int idx = tid + i * 256;
        const int t   = idx >> 10;
        const int r   = (idx >> 3) & 127;
        const int c16 = idx & 7;
        const __half* sp;
        int row;
        if (t == 0)      { sp = Ah; row = bm + r; }
        else if (t == 1) { sp = Al; row = bm + r; }
        else             { sp = Bw; row = bn + r; }
        const char* src = (const char*)sp +
            (((size_t)row * K + k0) << 1) + (c16 << 4);
        const uint32_t off = (r << 7) + (c16 << 4);
        const uint32_t dst = dbase + (t << 14) + SMEM_SWIZZLE_128B(off);
        CP_ASYNC16(dst, src);
    }
    CP_ASYNC_COMMIT();
}

__global__ __launch_bounds__(256, 1) void gemm_hmma16(
    const __half* __restrict__ Ah, const __half* __restrict__ Al,
    const __half* __restrict__ Bw,
    const float* __restrict__ bias, float* __restrict__ C,
    int M, int N, int K)
{
    extern __shared__ __align__(16) char smem[];
    const uint32_t data0 = (smem_to_u32(smem) + 1023) & ~1023u;

    const int tid  = threadIdx.x;
    const int lane = tid & 31;
    const int wid  = tid >> 5;
    const int warp_m = wid >> 2;
    const int warp_n = wid & 3;
    const int bm = blockIdx.y * 128;
    const int bn = blockIdx.x * 128;

    const uint32_t a_row = warp_m * 64 + (lane & 15);
    const uint32_t a_kb  = (uint32_t)(lane >> 4) << 4;
    const uint32_t b_row = warp_n * 32 + (lane & 7) + (((uint32_t)lane >> 4) << 3);
    const uint32_t b_kb  = (((uint32_t)lane >> 3) & 1) << 4;

    float acc[4][4][4];
#pragma unroll
    for (int mt = 0; mt < 4; mt++)
#pragma unroll
        for (int nt = 0; nt < 4; nt++)
#pragma unroll
            for (int r = 0; r < 4; r++) acc[mt][nt][r] = 0.0f;

    const int nchunks = K >> 6;
    load_chunk3(Ah, Al, Bw, bm, bn, K, 0, data0, tid);

    for (int c = 0; c < nchunks; c++) {
        if (c + 1 < nchunks) {
            load_chunk3(Ah, Al, Bw, bm, bn, K, (c + 1) << 6,
                        data0 + ((c + 1) & 1) * 49152, tid);
            asm volatile("cp.async.wait_group 1;" ::: "memory");
        } else {
            asm volatile("cp.async.wait_group 0;" ::: "memory");
        }
        __syncthreads();

        const uint32_t dbase = data0 + (c & 1) * 49152;
        const uint32_t sAh = dbase;
        const uint32_t sAl = dbase + 16384;
        const uint32_t sB  = dbase + 32768;

#pragma unroll
        for (int ks = 0; ks < 4; ks++) {
            const uint32_t kbyte = (uint32_t)ks << 5;

            uint32_t af_h[4][4], af_l[4][4];
#pragma unroll
            for (int mt = 0; mt < 4; mt++) {
                const uint32_t off = ((a_row + mt * 16) << 7) + kbyte + a_kb;
                const uint32_t sw = SMEM_SWIZZLE_128B(off);
                ldsm4(af_h[mt], sAh + sw);
                ldsm4(af_l[mt], sAl + sw);
            }
            uint32_t bf_[2][4];
#pragma unroll
            for (int ng = 0; ng < 2; ng++) {
                const uint32_t off = ((b_row + ng * 16) << 7) + kbyte + b_kb;
                ldsm4(bf_[ng], sB + SMEM_SWIZZLE_128B(off));
            }
#pragma unroll
            for (int mt = 0; mt < 4; mt++) {
#pragma unroll
                for (int nt = 0; nt < 4; nt++) {
                    const int ng = nt >> 1, lo = (nt & 1) * 2;
                    mma16816f(acc[mt][nt], af_h[mt], bf_[ng][lo], bf_[ng][lo + 1]);
                    mma16816f(acc[mt][nt], af_l[mt], bf_[ng][lo], bf_[ng][lo + 1]);
                }
            }
        }
        __syncthreads();
    }

    const int gm0 = bm + warp_m * 64 + (lane >> 2);
    const int gn0 = bn + warp_n * 32 + (lane & 3) * 2;
#pragma unroll
    for (int mt = 0; mt < 4; mt++) {
#pragma unroll
        for (int nt = 0; nt < 4; nt++) {
            const int gm = gm0 + mt * 16;
            const int gn = gn0 + nt * 8;
            const float b0 = bias[gn], b1 = bias[gn + 1];
            float2 v0 = make_float2(acc[mt][nt][0] + b0, acc[mt][nt][1] + b1);
            float2 v1 = make_float2(acc[mt][nt][2] + b0, acc[mt][nt][3] + b1);
            *(float2*)&C[(size_t)gm * N + gn]       = v0;
            *(float2*)&C[(size_t)(gm + 8) * N + gn] = v1;
        }
    }
}

// ---------------------------------------------------------------------------
// RoPE + split qkv -> q/k/v single fp16, layout [bh][t][hd]
// ---------------------------------------------------------------------------
__global__ __launch_bounds__(256) void rope_split_16(
    const float* __restrict__ qkv,
    __half* __restrict__ q16, __half* __restrict__ k16,
    __half* __restrict__ v16)
{
    const int idx = blockIdx.x * blockDim.x + threadIdx.x;
    const int i  = idx & 63;
    const int t  = (idx >> 6) & (T_ - 1);
    const int h  = (idx >> 17) & (H_ - 1);
    const int b  = idx >> 21;
    const int bh = idx >> 17;

    const float* src = qkv + ((size_t)(b * T_ + t)) * N1_ + h * (3 * HD_);
    const float q1 = src[i],        q2 = src[64 + i];
    const float k1 = src[128 + i],  k2 = src[192 + i];
    const float v1 = src[256 + i],  v2 = src[320 + i];

    const float theta = powf(10000.0f, -(float)i * (1.0f / 64.0f));
    const float ang = (float)t * theta;
    const float cs = cosf(ang), sn = sinf(ang);

    const size_t dst = ((size_t)bh * T_ + t) * HD_ + i;
    q16[dst]      = __float2half(q1 * cs - q2 * sn);
    q16[dst + 64] = __float2half(q1 * sn + q2 * cs);
    k16[dst]      = __float2half(k1 * cs - k2 * sn);
    k16[dst + 64] = __float2half(k1 * sn + k2 * cs);
    v16[dst]      = __float2half(v1);
    v16[dst + 64] = __float2half(v2);
}

// ---------------------------------------------------------------------------
// Causal flash attention, single fp16 Q/K/V/P, fp32 accum + softmax.
// CTA: 128 q-rows x Bc=64 kv, 8 warps x 16 q-rows.
// SMEM (272B padded rows): Q 34816 | 2 x { K 17408, V 17408 } = 104448 B.
// Epilogue emits fp16 hi/lo attn (A-operand of GEMM2).
// ---------------------------------------------------------------------------
#define FL_SMEM_BYTES 104448
#define FL_STRIDE 272

__device__ __forceinline__ void fl_load_kv16(
    const __half* K16, const __half* V16,
    size_t goff, uint32_t sbuf, int tid)
{
#pragma unroll
    for (int i = 0; i < 8; i++) {
        const int idx = tid + i * 256;
        const int arr = idx >> 10;          // 0:K 1:V
        const int r   = (idx >> 4) & 63;
        const int seg = idx & 15;
        const __half* p = arr ? V16 : K16;
        const char* src = (const char*)p + ((goff + (size_t)r * HD_) << 1) + (seg << 4);
        const uint32_t dst = sbuf + arr * 17408 + r * FL_STRIDE + (seg << 4);
        CP_ASYNC16(dst, src);
    }
    CP_ASYNC_COMMIT();
}

__global__ __launch_bounds__(256, 1) void flash_hmma16(
    const __half* __restrict__ Q16, const __half* __restrict__ K16,
    const __half* __restrict__ V16,
    __half* __restrict__ Oh, __half* __restrict__ Ol)
{
    extern __shared__ __align__(16) char smc[];
    const uint32_t sb  = smem_to_u32(smc);
    const uint32_t sQ  = sb;
    const uint32_t sKV = sb + 34816;            // + buf*34816

    const int tid  = threadIdx.x;
    const int lane = tid & 31;
    const int warp = tid >> 5;
    const int qt = 15 - (int)blockIdx.x;        // heavy blocks first
    const int bh = blockIdx.y;
    const int b = bh >> 4, h = bh & 15;
    const size_t gbase = (size_t)bh * T_ * HD_;

    // Q load
    {
        const size_t qoff = gbase + (size_t)qt * 128 * HD_;
#pragma unroll
        for (int i = 0; i < 8; i++) {
            const int idx = tid + i * 256;
            const int r   = (idx >> 4) & 127;
            const int seg = idx & 15;
            const char* src = (const char*)Q16 +
                ((qoff + (size_t)r * HD_) << 1) + (seg << 4);
            CP_ASYNC16(sQ + r * FL_STRIDE + (seg << 4), src);
        }
        CP_ASYNC_COMMIT();
    }
    // first KV tile
    fl_load_kv16(K16, V16, gbase, sKV, tid);

    const int r0w = warp * 16;
    const uint32_t aoff = (r0w + (lane & 15)) * FL_STRIDE + ((lane >> 4) << 4);
    const uint32_t boff = ((lane & 7) + ((lane >> 4) << 3)) * FL_STRIDE +
                          (((lane >> 3) & 1) << 4);
    const uint32_t vrow = (lane & 7) + (((lane >> 3) & 1) << 3);
    const uint32_t vcol = (lane >> 4) << 4;

    float o[16][4];
#pragma unroll
    for (int nt = 0; nt < 16; nt++)
#pragma unroll
        for (int r = 0; r < 4; r++) o[nt][r] = 0.0f;
    float m_[2] = {-1e30f, -1e30f};
    float l_[2] = {0.0f, 0.0f};

    const int ktmax = 2 * qt + 1;
    for (int kt = 0; kt <= ktmax; kt++) {
        if (kt > 0) __syncthreads();
        if (kt < ktmax) {
            fl_load_kv16(K16, V16, gbase + (size_t)(kt + 1) * 64 * HD_,
                         sKV + ((kt + 1) & 1) * 34816, tid);
            asm volatile("cp.async.wait_group 1;" ::: "memory");
        } else {
            asm volatile("cp.async.wait_group 0;" ::: "memory");
        }
        __syncthreads();

        const uint32_t kb = sKV + (kt & 1) * 34816;
        const uint32_t sK = kb, sV = kb + 17408;

        // ---- S = Q K^T (single fp16) ----
        float s[8][4];
#pragma unroll
        for (int nt = 0; nt < 8; nt++)
#pragma unroll
            for (int r = 0; r < 4; r++) s[nt][r] = 0.0f;

#pragma unroll
        for (int ks = 0; ks < 8; ks++) {
            const uint32_t kbyte = (uint32_t)ks << 5;
            uint32_t aq[4];
            ldsm4(aq, sQ + aoff + kbyte);
            uint32_t bk[4][4];
#pragma unroll
            for (int np = 0; np < 4; np++)
                ldsm4(bk[np], sK + boff + np * 16 * FL_STRIDE + kbyte);
#pragma unroll
            for (int nt = 0; nt < 8; nt++) {
                const int ng = nt >> 1, lo = (nt & 1) * 2;
                mma16816f(s[nt], aq, bk[ng][lo], bk[ng][lo + 1]);
            }
        }

        // ---- scale + mask + online softmax (fp32) ----
        const int qa = qt * 128 + r0w + (lane >> 2);
        const int qb = qa + 8;
        const bool dg = (kt >= 2 * qt);
#pragma unroll
        for (int nt = 0; nt < 8; nt++) {
            const int c0 = kt * 64 + nt * 8 + (lane & 3) * 2;
            s[nt][0] *= SCALE_; s[nt][1] *= SCALE_;
            s[nt][2] *= SCALE_; s[nt][3] *= SCALE_;
            if (dg) {
                if (c0     > qa) s[nt][0] = -1e30f;
                if (c0 + 1 > qa) s[nt][1] = -1e30f;
                if (c0     > qb) s[nt][2] = -1e30f;
                if (c0 + 1 > qb) s[nt][3] = -1e30f;
            }
        }
        float ma = -1e30f, mb = -1e30f;
#pragma unroll
        for (int nt = 0; nt < 8; nt++) {
            ma = fmaxf(ma, fmaxf(s[nt][0], s[nt][1]));
            mb = fmaxf(mb, fmaxf(s[nt][2], s[nt][3]));
        }
        ma = fmaxf(ma, __shfl_xor_sync(0xFFFFFFFF, ma, 1));
        ma = fmaxf(ma, __shfl_xor_sync(0xFFFFFFFF, ma, 2));
        mb = fmaxf(mb, __shfl_xor_sync(0xFFFFFFFF, mb, 1));
        mb = fmaxf(mb, __shfl_xor_sync(0xFFFFFFFF, mb, 2));
        const float mna = fmaxf(m_[0], ma), mnb = fmaxf(m_[1], mb);
        const float ca = __expf(m_[0] - mna), cb = __expf(m_[1] - mnb);
        float suma = 0.0f, sumb = 0.0f;
#pragma unroll
        for (int nt = 0; nt < 8; nt++) {
            s[nt][0] = __expf(s[nt][0] - mna); suma += s[nt][0];
            s[nt][1] = __expf(s[nt][1] - mna); suma += s[nt][1];
            s[nt][2] = __expf(s[nt][2] - mnb); sumb += s[nt][2];
            s[nt][3] = __expf(s[nt][3] - mnb); sumb += s[nt][3];
        }
        suma += __shfl_xor_sync(0xFFFFFFFF, suma, 1);
        suma += __shfl_xor_sync(0xFFFFFFFF, suma, 2);
        sumb += __shfl_xor_sync(0xFFFFFFFF, sumb, 1);
        sumb += __shfl_xor_sync(0xFFFFFFFF, sumb, 2);
        l_[0] = l_[0] * ca + suma;  m_[0] = mna;
        l_[1] = l_[1] * cb + sumb;  m_[1] = mnb;
#pragma unroll
        for (int nt = 0; nt < 16; nt++) {
            o[nt][0] *= ca; o[nt][1] *= ca;
            o[nt][2] *= cb; o[nt][3] *= cb;
        }

        // ---- P fragments (single fp16) ----
        uint32_t pa[4][4];
#pragma unroll
        for (int j = 0; j < 4; j++) {
            pa[j][0] = pack2h(s[2 * j][0],     s[2 * j][1]);
            pa[j][1] = pack2h(s[2 * j][2],     s[2 * j][3]);
            pa[j][2] = pack2h(s[2 * j + 1][0], s[2 * j + 1][1]);
            pa[j][3] = pack2h(s[2 * j + 1][2], s[2 * j + 1][3]);
        }

        // ---- O += P V (single fp16), V via ldmatrix.trans ----
#pragma unroll
        for (int j = 0; j < 4; j++) {
            const uint32_t rbase = (j * 16 + vrow) * FL_STRIDE + vcol;
#pragma unroll
            for (int dp = 0; dp < 8; dp++) {
                uint32_t vv[4];
                ldsm4t(vv, sV + rbase + dp * 32);
                mma16816f(o[dp * 2],     pa[j], vv[0], vv[1]);
                mma16816f(o[dp * 2 + 1], pa[j], vv[2], vv[3]);
            }
        }
    }

    // ---- epilogue: normalize, write fp16 hi/lo to [B*T][D] ----
    const float inva = 1.0f / l_[0], invb = 1.0f / l_[1];
    const int ta = qt * 128 + r0w + (lane >> 2);
    const size_t rowa = (size_t)(b * T_ + ta) * D_;
    const size_t rowb = rowa + 8 * D_;
    const int cb0 = h * HD_ + (lane & 3) * 2;
#pragma unroll
    for (int nt = 0; nt < 16; nt++) {
        const size_t ia = rowa + cb0 + nt * 8;
        const size_t ib = rowb + cb0 + nt * 8;
        uint32_t hA, lA, hB, lB;
        pack_hl16(o[nt][0] * inva, o[nt][1] * inva, hA, lA);
        pack_hl16(o[nt][2] * invb, o[nt][3] * invb, hB, lB);
        *(uint32_t*)(Oh + ia) = hA;  *(uint32_t*)(Ol + ia) = lA;
        *(uint32_t*)(Oh + ib) = hB;  *(uint32_t*)(Ol + ib) = lB;
    }
}

// ---------------------------------------------------------------------------
// kernel_launch
// ---------------------------------------------------------------------------
extern "C" void kernel_launch(void* const* d_in, const int* in_sizes, int n_in,
                              void* d_out, int out_size)
{
    const float* x     = (const float*)d_in[0];
    const float* w_qkv = (const float*)d_in[1];
    const float* b_qkv = (const float*)d_in[2];
    const float* w_out = (const float*)d_in[3];
    const float* b_out = (const float*)d_in[4];
    float* out = (float*)d_out;

    float* qkv;
    cudaGetSymbolAddress((void**)&qkv, g_qkv);
    __half *x16, *wq16, *ah, *al, *wo16, *q16, *k16, *v16;
    cudaGetSymbolAddress((void**)&x16,  g_x16);
    cudaGetSymbolAddress((void**)&wq16, g_wq16);
    cudaGetSymbolAddress((void**)&ah,   g_ah);
    cudaGetSymbolAddress((void**)&al,   g_al);
    cudaGetSymbolAddress((void**)&wo16, g_wo16);
    cudaGetSymbolAddress((void**)&q16,  g_q16);
    cudaGetSymbolAddress((void**)&k16,  g_k16);
    cudaGetSymbolAddress((void**)&v16,  g_v16);

    cudaFuncSetAttribute(gemm_ss,
                         cudaFuncAttributeMaxDynamicSharedMemorySize,
                         G1_SMEM_BYTES);
    cudaFuncSetAttribute(gemm_hmma16,
                         cudaFuncAttributeMaxDynamicSharedMemorySize,
                         G2_SMEM_BYTES);
    cudaFuncSetAttribute(flash_hmma16,
                         cudaFuncAttributeMaxDynamicSharedMemorySize,
                         FL_SMEM_BYTES);

    // 0) x, w_qkv -> fp16
    conv_fp16<<<((size_t)M_ * D_) / 1024, 256>>>(x, x16);
    conv_fp16<<<((size_t)N1_ * D_) / 1024, 256>>>(w_qkv, wq16);
    // 1) qkv = x16 @ wq16^T + b_qkv   (single x single fp16)
    gemm_ss<<<dim3(N1_ / 128, M_ / 128), 256, G1_SMEM_BYTES>>>(
        x16, wq16, b_qkv, qkv, M_, N1_, D_);
    // 2) RoPE + head split -> single fp16
    rope_split_16<<<(B_ * H_ * T_ * 64) / 256, 256>>>(qkv, q16, k16, v16);
    // 3) causal flash attention (single fp16) -> attn fp16 hi/lo
    flash_hmma16<<<dim3(16, B_ * H_), 256, FL_SMEM_BYTES>>>(
        q16, k16, v16, ah, al);
    // 4) w_out -> fp16 ; out = (ah+al) @ wo16^T + b_out  (2-term fp16)
    conv_fp16<<<((size_t)D_ * D_) / 1024, 256>>>(w_out, wo16);
    gemm_hmma16<<<dim3(D_ / 128, M_ / 128), 256, G2_SMEM_BYTES>>>(
        ah, al, wo16, b_out, out, M_, D_, D_);
}

// round 16
// speedup vs baseline: 3.2499x; 1.1307x over previous
#include <cuda_runtime.h>
#include <cuda_fp16.h>
#include <cstdint>
#include <math.h>

// Problem constants (fixed shapes)
#define B_   2
#define T_   2048
#define D_   2048
#define H_   16
#define HD_  128
#define M_   (B_ * T_)      // 4096 rows
#define N1_  (3 * D_)       // 6144 qkv cols
#define SCALE_ 0.022097086912079612f   // 2048^-0.5  (D, not head_dim!)

// ---------------------------------------------------------------------------
// Scratch (device globals — no allocation allowed)
// ---------------------------------------------------------------------------
__device__ __half g_qkv16[(size_t)M_ * N1_];       // 50.3 MB
__device__ __half g_x16[(size_t)M_ * D_];
__device__ __half g_wq16[(size_t)N1_ * D_];
__device__ __half g_attn16[(size_t)M_ * D_];
__device__ __half g_wo16[(size_t)D_ * D_];
#define QKV_ELEMS ((size_t)B_ * H_ * T_ * HD_)
__device__ __half g_q16[QKV_ELEMS];
__device__ __half g_k16[QKV_ELEMS];
__device__ __half g_v16[QKV_ELEMS];

// ---------------------------------------------------------------------------
// PTX helpers (family-portable: ldmatrix / mma.sync / cp.async)
// ---------------------------------------------------------------------------
__device__ __forceinline__ uint32_t smem_to_u32(const void* p) {
    uint32_t a;
    asm("{ .reg .u64 t; cvta.to.shared.u64 t, %1; cvt.u32.u64 %0, t; }"
        : "=r"(a) : "l"(p));
    return a;
}
#define SMEM_SWIZZLE_128B(off) ((off) ^ (((off) >> 3) & 0x70))

#define CP_ASYNC16(dst, src) \
    asm volatile("cp.async.cg.shared.global [%0], [%1], 16;" \
                 :: "r"((uint32_t)(dst)), "l"(src))
#define CP_ASYNC_COMMIT() asm volatile("cp.async.commit_group;" ::: "memory")

__device__ __forceinline__ void ldsm4(uint32_t* r, uint32_t addr) {
    asm volatile("ldmatrix.sync.aligned.m8n8.x4.shared.b16 {%0,%1,%2,%3}, [%4];"
                 : "=r"(r[0]), "=r"(r[1]), "=r"(r[2]), "=r"(r[3]) : "r"(addr));
}
__device__ __forceinline__ void ldsm4t(uint32_t* r, uint32_t addr) {
    asm volatile("ldmatrix.sync.aligned.m8n8.x4.trans.shared.b16 {%0,%1,%2,%3}, [%4];"
                 : "=r"(r[0]), "=r"(r[1]), "=r"(r[2]), "=r"(r[3]) : "r"(addr));
}

__device__ __forceinline__ void mma16816f(float* c, const uint32_t* a,
                                          uint32_t b0, uint32_t b1) {
    asm volatile(
        "mma.sync.aligned.m16n8k16.row.col.f32.f16.f16.f32 "
        "{%0,%1,%2,%3}, {%4,%5,%6,%7}, {%8,%9}, {%0,%1,%2,%3};"
        : "+f"(c[0]), "+f"(c[1]), "+f"(c[2]), "+f"(c[3])
        : "r"(a[0]), "r"(a[1]), "r"(a[2]), "r"(a[3]), "r"(b0), "r"(b1));
}

__device__ __forceinline__ uint32_t pack2h(float p0, float p1) {
    __half2 hh = __floats2half2_rn(p0, p1);
    return *(uint32_t*)&hh;
}

// ---------------------------------------------------------------------------
// fp32 -> fp16 convert, vectorized
// ---------------------------------------------------------------------------
__global__ __launch_bounds__(256) void conv_fp16(
    const float* __restrict__ src, __half* __restrict__ dst)
{
    const int i = blockIdx.x * 256 + threadIdx.x;   // float4 index
    float4 v = ((const float4*)src)[i];
    __half2 a = __floats2half2_rn(v.x, v.y);
    __half2 b = __floats2half2_rn(v.z, v.w);
    ((uint2*)dst)[i] = make_uint2(*(uint32_t*)&a, *(uint32_t*)&b);
}

// ---------------------------------------------------------------------------
// Single x single fp16 GEMM: C[M,N] = A16[M,K] @ W16[N,K]^T + bias
// CTA 128x128, BK=64, 8 warps (2m x 4n). 1 MMA per (mt,nt) per k16.
// SMEM per buffer (32KB): A 16K | B 16K; 128B rows, SW128. 2 buffers.
// Output type templated: __half (GEMM1 -> qkv16) or float (GEMM2 -> out).
// ---------------------------------------------------------------------------
#define G1_SMEM_BYTES (2 * 32768 + 1024)

__device__ __forceinline__ void load_chunk2(
    const __half* A, const __half* Bw,
    int bm, int bn, int K, int k0, uint32_t dbase, int tid)
{
#pragma unroll
    for (int i = 0; i < 8; i++) {
        const int idx = tid + i * 256;
        const int t   = idx >> 10;           // 0:A 1:B
        const int r   = (idx >> 3) & 127;
        const int c16 = idx & 7;
        const __half* sp = t ? Bw : A;
        const int row = (t ? bn : bm) + r;
        const char* src = (const char*)sp +
            (((size_t)row * K + k0) << 1) + (c16 << 4);
        const uint32_t off = (r << 7) + (c16 << 4);
        const uint32_t dst = dbase + (t << 14) + SMEM_SWIZZLE_128B(off);
        CP_ASYNC16(dst, src);
    }
    CP_ASYNC_COMMIT();
}

template <typename OutT>
__global__ __launch_bounds__(256, 1) void gemm_ss(
    const __half* __restrict__ A16, const __half* __restrict__ Bw,
    const float* __restrict__ bias, OutT* __restrict__ C,
    int M, int N, int K)
{
    extern __shared__ __align__(16) char smem[];
    const uint32_t data0 = (smem_to_u32(smem) + 1023) & ~1023u;

    const int tid  = threadIdx.x;
    const int lane = tid & 31;
    const int wid  = tid >> 5;
    const int warp_m = wid >> 2;
    const int warp_n = wid & 3;
    const int bm = blockIdx.y * 128;
    const int bn = blockIdx.x * 128;

    const uint32_t a_row = warp_m * 64 + (lane & 15);
    const uint32_t a_kb  = (uint32_t)(lane >> 4) << 4;
    const uint32_t b_row = warp_n * 32 + (lane & 7) + (((uint32_t)lane >> 4) << 3);
    const uint32_t b_kb  = (((uint32_t)lane >> 3) & 1) << 4;

    float acc[4][4][4];
#pragma unroll
    for (int mt = 0; mt < 4; mt++)
#pragma unroll
        for (int nt = 0; nt < 4; nt++)
#pragma unroll
            for (int r = 0; r < 4; r++) acc[mt][nt][r] = 0.0f;

    const int nchunks = K >> 6;
    load_chunk2(A16, Bw, bm, bn, K, 0, data0, tid);

    for (int c = 0; c < nchunks; c++) {
        if (c + 1 < nchunks) {
            load_chunk2(A16, Bw, bm, bn, K, (c + 1) << 6,
                        data0 + ((c + 1) & 1) * 32768, tid);
            asm volatile("cp.async.wait_group 1;" ::: "memory");
        } else {
            asm volatile("cp.async.wait_group 0;" ::: "memory");
        }
        __syncthreads();

        const uint32_t dbase = data0 + (c & 1) * 32768;
        const uint32_t sA = dbase;
        const uint32_t sB = dbase + 16384;

#pragma unroll
        for (int ks = 0; ks < 4; ks++) {
            const uint32_t kbyte = (uint32_t)ks << 5;

            uint32_t af_[4][4];
#pragma unroll
            for (int mt = 0; mt < 4; mt++) {
                const uint32_t off = ((a_row + mt * 16) << 7) + kbyte + a_kb;
                ldsm4(af_[mt], sA + SMEM_SWIZZLE_128B(off));
            }
            uint32_t bf_[2][4];
#pragma unroll
            for (int ng = 0; ng < 2; ng++) {
                const uint32_t off = ((b_row + ng * 16) << 7) + kbyte + b_kb;
                ldsm4(bf_[ng], sB + SMEM_SWIZZLE_128B(off));
            }
#pragma unroll
            for (int mt = 0; mt < 4; mt++) {
#pragma unroll
                for (int nt = 0; nt < 4; nt++) {
                    const int ng = nt >> 1, lo = (nt & 1) * 2;
                    mma16816f(acc[mt][nt], af_[mt], bf_[ng][lo], bf_[ng][lo + 1]);
                }
            }
        }
        __syncthreads();
    }

    const int gm0 = bm + warp_m * 64 + (lane >> 2);
    const int gn0 = bn + warp_n * 32 + (lane & 3) * 2;
#pragma unroll
    for (int mt = 0; mt < 4; mt++) {
#pragma unroll
        for (int nt = 0; nt < 4; nt++) {
            const int gm = gm0 + mt * 16;
            const int gn = gn0 + nt * 8;
            const float b0 = bias[gn], b1 = bias[gn + 1];
            const float v00 = acc[mt][nt][0] + b0, v01 = acc[mt][nt][1] + b1;
            const float v10 = acc[mt][nt][2] + b0, v11 = acc[mt][nt][3] + b1;
            if constexpr (sizeof(OutT) == 4) {
                *(float2*)&C[(size_t)gm * N + gn] = make_float2(v00, v01);
                *(float2*)&C[(size_t)(gm + 8) * N + gn] = make_float2(v10, v11);
            } else {
                *(uint32_t*)&C[(size_t)gm * N + gn] = pack2h(v00, v01);
                *(uint32_t*)&C[(size_t)(gm + 8) * N + gn] = pack2h(v10, v11);
            }
        }
    }
}

// ---------------------------------------------------------------------------
// RoPE + split qkv16 -> q/k/v single fp16, layout [bh][t][hd]
// ---------------------------------------------------------------------------
__global__ __launch_bounds__(256) void rope_split_16(
    const __half* __restrict__ qkv,
    __half* __restrict__ q16, __half* __restrict__ k16,
    __half* __restrict__ v16)
{
    const int idx = blockIdx.x * blockDim.x + threadIdx.x;
    const int i  = idx & 63;
    const int t  = (idx >> 6) & (T_ - 1);
    const int h  = (idx >> 17) & (H_ - 1);
    const int b  = idx >> 21;
    const int bh = idx >> 17;

    const __half* src = qkv + ((size_t)(b * T_ + t)) * N1_ + h * (3 * HD_);
    const float q1 = __half2float(src[i]),       q2 = __half2float(src[64 + i]);
    const float k1 = __half2float(src[128 + i]), k2 = __half2float(src[192 + i]);
    const __half v1 = src[256 + i], v2 = src[320 + i];

    const float theta = powf(10000.0f, -(float)i * (1.0f / 64.0f));
    const float ang = (float)t * theta;
    const float cs = cosf(ang), sn = sinf(ang);

    const size_t dst = ((size_t)bh * T_ + t) * HD_ + i;
    q16[dst]      = __float2half(q1 * cs - q2 * sn);
    q16[dst + 64] = __float2half(q1 * sn + q2 * cs);
    k16[dst]      = __float2half(k1 * cs - k2 * sn);
    k16[dst + 64] = __float2half(k1 * sn + k2 * cs);
    v16[dst]      = v1;
    v16[dst + 64] = v2;
}

// ---------------------------------------------------------------------------
// Causal flash attention, single fp16 Q/K/V/P, fp32 accum + softmax.
// CTA: 128 q-rows x Bc=64 kv, 8 warps x 16 q-rows.
// SMEM (272B padded rows): Q 34816 | 2 x { K 17408, V 17408 } = 104448 B.
// Epilogue emits single fp16 attn [B*T][D].
// ---------------------------------------------------------------------------
#define FL_SMEM_BYTES 104448
#define FL_STRIDE 272

__device__ __forceinline__ void fl_load_kv16(
    const __half* K16, const __half* V16,
    size_t goff, uint32_t sbuf, int tid)
{
#pragma unroll
    for (int i = 0; i < 8; i++) {
        const int idx = tid + i * 256;
        const int arr = idx >> 10;          // 0:K 1:V
        const int r   = (idx >> 4) & 63;
        const int seg = idx & 15;
        const __half* p = arr ? V16 : K16;
        const char* src = (const char*)p + ((goff + (size_t)r * HD_) << 1) + (seg << 4);
        const uint32_t dst = sbuf + arr * 17408 + r * FL_STRIDE + (seg << 4);
        CP_ASYNC16(dst, src);
    }
    CP_ASYNC_COMMIT();
}

__global__ __launch_bounds__(256, 1) void flash_hmma16(
    const __half* __restrict__ Q16, const __half* __restrict__ K16,
    const __half* __restrict__ V16, __half* __restrict__ O16)
{
    extern __shared__ __align__(16) char smc[];
    const uint32_t sb  = smem_to_u32(smc);
    const uint32_t sQ  = sb;
    const uint32_t sKV = sb + 34816;            // + buf*34816

    const int tid  = threadIdx.x;
    const int lane = tid & 31;
    const int warp = tid >> 5;
    const int qt = 15 - (int)blockIdx.x;        // heavy blocks first
    const int bh = blockIdx.y;
    const int b = bh >> 4, h = bh & 15;
    const size_t gbase = (size_t)bh * T_ * HD_;

    // Q load
    {
        const size_t qoff = gbase + (size_t)qt * 128 * HD_;
#pragma unroll
        for (int i = 0; i < 8; i++) {
            const int idx = tid + i * 256;
            const int r   = (idx >> 4) & 127;
            const int seg = idx & 15;
            const char* src = (const char*)Q16 +
                ((qoff + (size_t)r * HD_) << 1) + (seg << 4);
            CP_ASYNC16(sQ + r * FL_STRIDE + (seg << 4), src);
        }
        CP_ASYNC_COMMIT();
    }
    fl_load_kv16(K16, V16, gbase, sKV, tid);

    const int r0w = warp * 16;
    const uint32_t aoff = (r0w + (lane & 15)) * FL_STRIDE + ((lane >> 4) << 4);
    const uint32_t boff = ((lane & 7) + ((lane >> 4) << 3)) * FL_STRIDE +
                          (((lane >> 3) & 1) << 4);
    const uint32_t vrow = (lane & 7) + (((lane >> 3) & 1) << 3);
    const uint32_t vcol = (lane >> 4) << 4;

    float o[16][4];
#pragma unroll
    for (int nt = 0; nt < 16; nt++)
#pragma unroll
        for (int r = 0; r < 4; r++) o[nt][r] = 0.0f;
    float m_[2] = {-1e30f, -1e30f};
    float l_[2] = {0.0f, 0.0f};

    const int ktmax = 2 * qt + 1;
    for (int kt = 0; kt <= ktmax; kt++) {
        if (kt > 0) __syncthreads();
        if (kt < ktmax) {
            fl_load_kv16(K16, V16, gbase + (size_t)(kt + 1) * 64 * HD_,
                         sKV + ((kt + 1) & 1) * 34816, tid);
            asm volatile("cp.async.wait_group 1;" ::: "memory");
        } else {
            asm volatile("cp.async.wait_group 0;" ::: "memory");
        }
        __syncthreads();

        const uint32_t kb = sKV + (kt & 1) * 34816;
        const uint32_t sK = kb, sV = kb + 17408;

        // ---- S = Q K^T (single fp16) ----
        float s[8][4];
#pragma unroll
        for (int nt = 0; nt < 8; nt++)
#pragma unroll
            for (int r = 0; r < 4; r++) s[nt][r] = 0.0f;

#pragma unroll
        for (int ks = 0; ks < 8; ks++) {
            const uint32_t kbyte = (uint32_t)ks << 5;
            uint32_t aq[4];
            ldsm4(aq, sQ + aoff + kbyte);
            uint32_t bk[4][4];
#pragma unroll
            for (int np = 0; np < 4; np++)
                ldsm4(bk[np], sK + boff + np * 16 * FL_STRIDE + kbyte);
#pragma unroll
            for (int nt = 0; nt < 8; nt++) {
                const int ng = nt >> 1, lo = (nt & 1) * 2;
                mma16816f(s[nt], aq, bk[ng][lo], bk[ng][lo + 1]);
            }
        }

        // ---- scale + mask + online softmax (fp32) ----
        const int qa = qt * 128 + r0w + (lane >> 2);
        const int qb = qa + 8;
        const bool dg = (kt >= 2 * qt);
#pragma unroll
        for (int nt = 0; nt < 8; nt++) {
            const int c0 = kt * 64 + nt * 8 + (lane & 3) * 2;
            s[nt][0] *= SCALE_; s[nt][1] *= SCALE_;
            s[nt][2] *= SCALE_; s[nt][3] *= SCALE_;
            if (dg) {
                if (c0     > qa) s[nt][0] = -1e30f;
                if (c0 + 1 > qa) s[nt][1] = -1e30f;
                if (c0     > qb) s[nt][2] = -1e30f;
                if (c0 + 1 > qb) s[nt][3] = -1e30f;
            }
        }
        float ma = -1e30f, mb = -1e30f;
#pragma unroll
        for (int nt = 0; nt < 8; nt++) {
            ma = fmaxf(ma, fmaxf(s[nt][0], s[nt][1]));
            mb = fmaxf(mb, fmaxf(s[nt][2], s[nt][3]));
        }
        ma = fmaxf(ma, __shfl_xor_sync(0xFFFFFFFF, ma, 1));
        ma = fmaxf(ma, __shfl_xor_sync(0xFFFFFFFF, ma, 2));
        mb = fmaxf(mb, __shfl_xor_sync(0xFFFFFFFF, mb, 1));
        mb = fmaxf(mb, __shfl_xor_sync(0xFFFFFFFF, mb, 2));
        const float mna = fmaxf(m_[0], ma), mnb = fmaxf(m_[1], mb);
        const float ca = __expf(m_[0] - mna), cb = __expf(m_[1] - mnb);
        float suma = 0.0f, sumb = 0.0f;
#pragma unroll
        for (int nt = 0; nt < 8; nt++) {
            s[nt][0] = __expf(s[nt][0] - mna); suma += s[nt][0];
            s[nt][1] = __expf(s[nt][1] - mna); suma += s[nt][1];
            s[nt][2] = __expf(s[nt][2] - mnb); sumb += s[nt][2];
            s[nt][3] = __expf(s[nt][3] - mnb); sumb += s[nt][3];
        }
        suma += __shfl_xor_sync(0xFFFFFFFF, suma, 1);
        suma += __shfl_xor_sync(0xFFFFFFFF, suma, 2);
        sumb += __shfl_xor_sync(0xFFFFFFFF, sumb, 1);
        sumb += __shfl_xor_sync(0xFFFFFFFF, sumb, 2);
        l_[0] = l_[0] * ca + suma;  m_[0] = mna;
        l_[1] = l_[1] * cb + sumb;  m_[1] = mnb;
#pragma unroll
        for (int nt = 0; nt < 16; nt++) {
            o[nt][0] *= ca; o[nt][1] *= ca;
            o[nt][2] *= cb; o[nt][3] *= cb;
        }

        // ---- P fragments (single fp16) ----
        uint32_t pa[4][4];
#pragma unroll
        for (int j = 0; j < 4; j++) {
            pa[j][0] = pack2h(s[2 * j][0],     s[2 * j][1]);
            pa[j][1] = pack2h(s[2 * j][2],     s[2 * j][3]);
            pa[j][2] = pack2h(s[2 * j + 1][0], s[2 * j + 1][1]);
            pa[j][3] = pack2h(s[2 * j + 1][2], s[2 * j + 1][3]);
        }

        // ---- O += P V (single fp16), V via ldmatrix.trans ----
#pragma unroll
        for (int j = 0; j < 4; j++) {
            const uint32_t rbase = (j * 16 + vrow) * FL_STRIDE + vcol;
#pragma unroll
            for (int dp = 0; dp < 8; dp++) {
                uint32_t vv[4];
                ldsm4t(vv, sV + rbase + dp * 32);
                mma16816f(o[dp * 2],     pa[j], vv[0], vv[1]);
                mma16816f(o[dp * 2 + 1], pa[j], vv[2], vv[3]);
            }
        }
    }

    // ---- epilogue: normalize, write single fp16 to [B*T][D] ----
    const float inva = 1.0f / l_[0], invb = 1.0f / l_[1];
    const int ta = qt * 128 + r0w + (lane >> 2);
    const size_t rowa = (size_t)(b * T_ + ta) * D_;
    const size_t rowb = rowa + 8 * D_;
    const int cb0 = h * HD_ + (lane & 3) * 2;
#pragma unroll
    for (int nt = 0; nt < 16; nt++) {
        *(uint32_t*)(O16 + rowa + cb0 + nt * 8) =
            pack2h(o[nt][0] * inva, o[nt][1] * inva);
        *(uint32_t*)(O16 + rowb + cb0 + nt * 8) =
            pack2h(o[nt][2] * invb, o[nt][3] * invb);
    }
}

// ---------------------------------------------------------------------------
// kernel_launch
// ---------------------------------------------------------------------------
extern "C" void kernel_launch(void* const* d_in, const int* in_sizes, int n_in,
                              void* d_out, int out_size)
{
    const float* x     = (const float*)d_in[0];
    const float* w_qkv = (const float*)d_in[1];
    const float* b_qkv = (const float*)d_in[2];
    const float* w_out = (const float*)d_in[3];
    const float* b_out = (const float*)d_in[4];
    float* out = (float*)d_out;

    __half *qkv16, *x16, *wq16, *attn16, *wo16, *q16, *k16, *v16;
    cudaGetSymbolAddress((void**)&qkv16,  g_qkv16);
    cudaGetSymbolAddress((void**)&x16,    g_x16);
    cudaGetSymbolAddress((void**)&wq16,   g_wq16);
    cudaGetSymbolAddress((void**)&attn16, g_attn16);
    cudaGetSymbolAddress((void**)&wo16,   g_wo16);
    cudaGetSymbolAddress((void**)&q16,    g_q16);
    cudaGetSymbolAddress((void**)&k16,    g_k16);
    cudaGetSymbolAddress((void**)&v16,    g_v16);

    cudaFuncSetAttribute(gemm_ss<__half>,
                         cudaFuncAttributeMaxDynamicSharedMemorySize,
                         G1_SMEM_BYTES);
    cudaFuncSetAttribute(gemm_ss<float>,
                         cudaFuncAttributeMaxDynamicSharedMemorySize,
                         G1_SMEM_BYTES);
    cudaFuncSetAttribute(flash_hmma16,
                         cudaFuncAttributeMaxDynamicSharedMemorySize,
                         FL_SMEM_BYTES);

    // 0) x, w_qkv -> fp16
    conv_fp16<<<((size_t)M_ * D_) / 1024, 256>>>(x, x16);
    conv_fp16<<<((size_t)N1_ * D_) / 1024, 256>>>(w_qkv, wq16);
    // 1) qkv16 = x16 @ wq16^T + b_qkv   (single x single fp16, fp16 out)
    gemm_ss<__half><<<dim3(N1_ / 128, M_ / 128), 256, G1_SMEM_BYTES>>>(
        x16, wq16, b_qkv, qkv16, M_, N1_, D_);
    // 2) RoPE + head split -> single fp16
    rope_split_16<<<(B_ * H_ * T_ * 64) / 256, 256>>>(qkv16, q16, k16, v16);
    // 3) causal flash attention (single fp16) -> attn fp16
    flash_hmma16<<<dim3(16, B_ * H_), 256, FL_SMEM_BYTES>>>(
        q16, k16, v16, attn16);
    // 4) w_out -> fp16 ; out = attn16 @ wo16^T + b_out  (single x single)
    conv_fp16<<<((size_t)D_ * D_) / 1024, 256>>>(w_out, wo16);
    gemm_ss<float><<<dim3(D_ / 128, M_ / 128), 256, G1_SMEM_BYTES>>>(
        attn16, wo16, b_out, out, M_, D_, D_);
}